// round 1
// baseline (speedup 1.0000x reference)
#include <cuda_runtime.h>
#include <math.h>

#define B_SZ   4
#define SEQ    4096
#define DMODEL 512
#define DIN    1024
#define NH     16
#define HD     64
#define DS     64
#define NCH    16
#define CHUNK  256
#define CONVDIM 1152
#define DPROJ  2192
#define NTOK   (B_SZ*SEQ)   // 16384

// ---------------- scratch (device globals; no runtime alloc) ----------------
__device__ float g_zx[(size_t)NTOK*DPROJ];        // in_proj output
__device__ float g_xbc[(size_t)NTOK*CONVDIM];     // conv+silu output
__device__ float g_xdt[(size_t)NTOK*DIN];         // xh * dt
__device__ float g_dt[NTOK*NH];
__device__ float g_acum[B_SZ*NCH*NH*CHUNK];       // per-chunk inclusive cumsum of dt*A
__device__ float g_states[B_SZ*NCH*NH*HD*DS];     // per-chunk states [b,c,h,p,n]
__device__ float g_prefix[B_SZ*NCH*NH*HD*DS];     // inter-chunk prefix states
__device__ float g_y[(size_t)NTOK*DIN];           // y (diag, then +off, then gated/normed)

// ---------------- SGEMM: C[M,N] = A[M,K] @ B[N,K]^T  (both K-major) ----------------
__global__ __launch_bounds__(256) void sgemm_nt(const float* __restrict__ A,
                                                const float* __restrict__ Bw,
                                                float* __restrict__ C,
                                                int M, int N, int K) {
    __shared__ float As[16][132];   // [k][m], padded
    __shared__ float Bs[16][68];    // [k][n], padded
    int tid = threadIdx.x;
    int tx = tid & 15, ty = tid >> 4;          // 16x16 thread grid
    int rowBase = blockIdx.y * 128;
    int colBase = blockIdx.x * 64;

    float acc[8][4];
#pragma unroll
    for (int i = 0; i < 8; i++)
#pragma unroll
        for (int j = 0; j < 4; j++) acc[i][j] = 0.f;

    for (int k0 = 0; k0 < K; k0 += 16) {
        // A tile: 128 rows x 16 k = 512 float4; 2 per thread
#pragma unroll
        for (int q = 0; q < 2; q++) {
            int i = tid + q * 256;         // float4 index
            int r = i >> 2;                // row 0..127
            int kq = (i & 3) * 4;
            float4 a4 = *(const float4*)&A[(size_t)(rowBase + r) * K + k0 + kq];
            As[kq + 0][r] = a4.x; As[kq + 1][r] = a4.y;
            As[kq + 2][r] = a4.z; As[kq + 3][r] = a4.w;
        }
        // B tile: 64 rows x 16 k = 256 float4; 1 per thread
        {
            int i = tid;
            int r = i >> 2;
            int kq = (i & 3) * 4;
            int nrow = colBase + r;
            float4 b4 = make_float4(0.f, 0.f, 0.f, 0.f);
            if (nrow < N) b4 = *(const float4*)&Bw[(size_t)nrow * K + k0 + kq];
            Bs[kq + 0][r] = b4.x; Bs[kq + 1][r] = b4.y;
            Bs[kq + 2][r] = b4.z; Bs[kq + 3][r] = b4.w;
        }
        __syncthreads();
#pragma unroll
        for (int k = 0; k < 16; k++) {
            float ar[8], br[4];
#pragma unroll
            for (int i = 0; i < 8; i++) ar[i] = As[k][ty * 8 + i];
#pragma unroll
            for (int j = 0; j < 4; j++) br[j] = Bs[k][tx * 4 + j];
#pragma unroll
            for (int i = 0; i < 8; i++)
#pragma unroll
                for (int j = 0; j < 4; j++) acc[i][j] += ar[i] * br[j];
        }
        __syncthreads();
    }
#pragma unroll
    for (int i = 0; i < 8; i++) {
        int row = rowBase + ty * 8 + i;
#pragma unroll
        for (int j = 0; j < 4; j++) {
            int col = colBase + tx * 4 + j;
            if (col < N) C[(size_t)row * N + col] = acc[i][j];
        }
    }
}

// ---------------- causal conv1d (width 4) + SiLU ----------------
__global__ __launch_bounds__(256) void conv_kernel(const float* __restrict__ zx,
                                                   const float* __restrict__ conv_w,
                                                   const float* __restrict__ conv_b,
                                                   float* __restrict__ xbc) {
    int idx = blockIdx.x * 256 + threadIdx.x;      // over NTOK*CONVDIM
    int c = idx % CONVDIM;
    int bl = idx / CONVDIM;
    int l = bl & (SEQ - 1);
    int b = bl >> 12;
    float acc = conv_b[c];
#pragma unroll
    for (int k = 0; k < 4; k++) {
        int ls = l - 3 + k;
        if (ls >= 0)
            acc += zx[(size_t)(b * SEQ + ls) * DPROJ + DIN + c] * conv_w[c * 4 + k];
    }
    xbc[idx] = acc / (1.f + expf(-acc));   // silu
}

// ---------------- dt = softplus(raw + bias); a = dt*A; per-chunk inclusive cumsum ----------------
__global__ __launch_bounds__(256) void dt_acum_kernel(const float* __restrict__ zx,
                                                      const float* __restrict__ dt_bias,
                                                      const float* __restrict__ A_log,
                                                      float* __restrict__ dtp,
                                                      float* __restrict__ acum) {
    int bc = blockIdx.x;            // b*NCH + c
    int h = blockIdx.y;
    int b = bc >> 4, c = bc & 15;
    int l = threadIdx.x;
    int row = b * SEQ + c * CHUNK + l;
    float x = zx[(size_t)row * DPROJ + (DPROJ - NH) + h] + dt_bias[h];
    float dtv = (x > 20.f) ? x : log1pf(expf(x));
    dtp[row * NH + h] = dtv;
    float a = -expf(A_log[h]) * dtv;

    __shared__ float s[CHUNK];
    s[l] = a;
    __syncthreads();
#pragma unroll
    for (int off = 1; off < CHUNK; off <<= 1) {
        float v = (l >= off) ? s[l - off] : 0.f;
        __syncthreads();
        s[l] += v;
        __syncthreads();
    }
    acum[(bc * NH + h) * CHUNK + l] = s[l];
}

// ---------------- xdt = xh * dt ----------------
__global__ __launch_bounds__(256) void xdt_kernel(const float* __restrict__ xbc,
                                                  const float* __restrict__ dtp,
                                                  float* __restrict__ xdt) {
    int idx = blockIdx.x * 256 + threadIdx.x;  // over NTOK*DIN
    int row = idx >> 10;
    int d = idx & 1023;
    int h = d >> 6;
    xdt[idx] = xbc[(size_t)row * CONVDIM + d] * dtp[row * NH + h];
}

// ---------------- intra-chunk: Y_diag[l,p] = sum_{s<=l} (C_l.B_s) exp(ac_l-ac_s) xdt[s,p] ----------------
__global__ __launch_bounds__(256) void ydiag_kernel(const float* __restrict__ xbc,
                                                    const float* __restrict__ xdt,
                                                    const float* __restrict__ acum,
                                                    float* __restrict__ y) {
    int bc = blockIdx.x, h = blockIdx.y;
    int b = bc >> 4, c = bc & 15;
    int l = threadIdx.x;
    int rowBase = b * SEQ + c * CHUNK;

    __shared__ float sAc[CHUNK];
    __shared__ float sB[64][64];
    __shared__ float sX[64][64];

    sAc[l] = acum[(bc * NH + h) * CHUNK + l];

    float creg[64];
    {
        const float4* crow = (const float4*)&xbc[(size_t)(rowBase + l) * CONVDIM + DIN + DS];
#pragma unroll
        for (int q = 0; q < 16; q++) {
            float4 v = crow[q];
            creg[q * 4 + 0] = v.x; creg[q * 4 + 1] = v.y;
            creg[q * 4 + 2] = v.z; creg[q * 4 + 3] = v.w;
        }
    }
    float acc[64];
#pragma unroll
    for (int p = 0; p < 64; p++) acc[p] = 0.f;

    __syncthreads();
    float aL = sAc[l];

    for (int st = 0; st < 4; st++) {
        // load 64 source rows of B and xdt
#pragma unroll
        for (int q = 0; q < 4; q++) {
            int i = l + q * 256;           // float4 index 0..1023
            int r = i >> 4;                // row 0..63
            int nq = (i & 15) * 4;
            int srow = rowBase + st * 64 + r;
            *(float4*)&sB[r][nq] = *(const float4*)&xbc[(size_t)srow * CONVDIM + DIN + nq];
            *(float4*)&sX[r][nq] = *(const float4*)&xdt[(size_t)srow * DIN + h * HD + nq];
        }
        __syncthreads();
        int smax = l - st * 64 + 1;        // count of valid ss in this tile
        if (smax > 64) smax = 64;
        for (int ss = 0; ss < smax; ss++) {
            float cb = 0.f;
#pragma unroll
            for (int n = 0; n < 64; n++) cb += creg[n] * sB[ss][n];
            float w = __expf(aL - sAc[st * 64 + ss]) * cb;
#pragma unroll
            for (int p = 0; p < 64; p++) acc[p] += w * sX[ss][p];
        }
        __syncthreads();
    }
    float* yrow = &g_y[0];  // silence unused warning pattern; real write below
    (void)yrow;
    float* yout = &y[(size_t)(rowBase + l) * DIN + h * HD];
#pragma unroll
    for (int p = 0; p < 64; p += 4) {
        float4 v = make_float4(acc[p], acc[p + 1], acc[p + 2], acc[p + 3]);
        *(float4*)&yout[p] = v;
    }
}

// ---------------- per-chunk states[p,n] = sum_l exp(ac_end-ac_l) xdt[l,p] B[l,n] ----------------
__global__ __launch_bounds__(256) void states_kernel(const float* __restrict__ xbc,
                                                     const float* __restrict__ xdt,
                                                     const float* __restrict__ acum,
                                                     float* __restrict__ states) {
    int bc = blockIdx.x, h = blockIdx.y;
    int b = bc >> 4, c = bc & 15;
    int t = threadIdx.x;
    int rowBase = b * SEQ + c * CHUNK;

    __shared__ float sDec[CHUNK];
    __shared__ float sB[64][64];
    __shared__ float sX[64][64];

    {
        float aEnd = acum[(bc * NH + h) * CHUNK + (CHUNK - 1)];
        sDec[t] = __expf(aEnd - acum[(bc * NH + h) * CHUNK + t]);
    }
    int p = t >> 2;
    int n0 = (t & 3) * 16;
    float acc[16];
#pragma unroll
    for (int j = 0; j < 16; j++) acc[j] = 0.f;
    __syncthreads();

    for (int st = 0; st < 4; st++) {
#pragma unroll
        for (int q = 0; q < 4; q++) {
            int i = t + q * 256;
            int r = i >> 4;
            int nq = (i & 15) * 4;
            int srow = rowBase + st * 64 + r;
            *(float4*)&sB[r][nq] = *(const float4*)&xbc[(size_t)srow * CONVDIM + DIN + nq];
            *(float4*)&sX[r][nq] = *(const float4*)&xdt[(size_t)srow * DIN + h * HD + nq];
        }
        __syncthreads();
        for (int ss = 0; ss < 64; ss++) {
            float wx = sDec[st * 64 + ss] * sX[ss][p];
#pragma unroll
            for (int j = 0; j < 16; j++) acc[j] += wx * sB[ss][n0 + j];
        }
        __syncthreads();
    }
    float* out = &states[((size_t)(bc * NH + h)) * (HD * DS) + p * DS + n0];
#pragma unroll
    for (int j = 0; j < 16; j += 4) {
        float4 v = make_float4(acc[j], acc[j + 1], acc[j + 2], acc[j + 3]);
        *(float4*)&out[j] = v;
    }
}

// ---------------- inter-chunk sequential scan: P[c] = exp(sumA[c-1])*P[c-1] + states[c-1] ----------------
__global__ __launch_bounds__(256) void scan_kernel(const float* __restrict__ acum,
                                                   const float* __restrict__ states,
                                                   float* __restrict__ prefix) {
    int b = blockIdx.x, h = blockIdx.y, t = threadIdx.x;
    float S[16];
#pragma unroll
    for (int j = 0; j < 16; j++) S[j] = 0.f;
    for (int c = 0; c < NCH; c++) {
        size_t base = ((size_t)((b * NCH + c) * NH + h)) * (HD * DS) + t * 16;
#pragma unroll
        for (int j = 0; j < 16; j += 4) {
            float4 v = make_float4(S[j], S[j + 1], S[j + 2], S[j + 3]);
            *(float4*)&prefix[base + j] = v;
        }
        float cs = __expf(acum[((b * NCH + c) * NH + h) * CHUNK + (CHUNK - 1)]);
#pragma unroll
        for (int j = 0; j < 16; j += 4) {
            float4 sv = *(const float4*)&states[base + j];
            S[j + 0] = cs * S[j + 0] + sv.x;
            S[j + 1] = cs * S[j + 1] + sv.y;
            S[j + 2] = cs * S[j + 2] + sv.z;
            S[j + 3] = cs * S[j + 3] + sv.w;
        }
    }
}

// ---------------- Y_off + D*xh combine:  y += exp(ac_l) * C_l @ P   + D_h * xh ----------------
__global__ __launch_bounds__(256) void yoff_kernel(const float* __restrict__ xbc,
                                                   const float* __restrict__ prefix,
                                                   const float* __restrict__ acum,
                                                   const float* __restrict__ Dv,
                                                   float* __restrict__ y) {
    int bc = blockIdx.x, h = blockIdx.y;
    int b = bc >> 4, c = bc & 15;
    int l = threadIdx.x;
    int rowBase = b * SEQ + c * CHUNK;

    __shared__ float sP[HD * DS];   // 4096 floats
    {
        const float4* src = (const float4*)&prefix[((size_t)(bc * NH + h)) * (HD * DS)];
#pragma unroll
        for (int q = 0; q < 4; q++) ((float4*)sP)[l + q * 256] = src[l + q * 256];
    }
    float creg[64];
    {
        const float4* crow = (const float4*)&xbc[(size_t)(rowBase + l) * CONVDIM + DIN + DS];
#pragma unroll
        for (int q = 0; q < 16; q++) {
            float4 v = crow[q];
            creg[q * 4 + 0] = v.x; creg[q * 4 + 1] = v.y;
            creg[q * 4 + 2] = v.z; creg[q * 4 + 3] = v.w;
        }
    }
    float aE = __expf(acum[(bc * NH + h) * CHUNK + l]);
    float Dh = Dv[h];
    __syncthreads();

    const float4* xh4 = (const float4*)&xbc[(size_t)(rowBase + l) * CONVDIM + h * HD];
    float4* y4 = (float4*)&y[(size_t)(rowBase + l) * DIN + h * HD];
#pragma unroll
    for (int p0 = 0; p0 < 64; p0 += 4) {
        float4 xh = xh4[p0 / 4];
        float4 yd = y4[p0 / 4];
        float o[4];
#pragma unroll
        for (int i = 0; i < 4; i++) {
            float s = 0.f;
#pragma unroll
            for (int n = 0; n < 64; n++) s += creg[n] * sP[(p0 + i) * DS + n];
            float xv = (i == 0) ? xh.x : (i == 1) ? xh.y : (i == 2) ? xh.z : xh.w;
            float dv = (i == 0) ? yd.x : (i == 1) ? yd.y : (i == 2) ? yd.z : yd.w;
            o[i] = dv + aE * s + Dh * xv;
        }
        y4[p0 / 4] = make_float4(o[0], o[1], o[2], o[3]);
    }
}

// ---------------- gate with silu(z) + RMSNorm ----------------
__global__ __launch_bounds__(256) void gate_norm_kernel(const float* __restrict__ zx,
                                                        const float* __restrict__ norm_w,
                                                        float* __restrict__ y) {
    int row = blockIdx.x;
    int t = threadIdx.x;
    float4 yv = ((const float4*)&y[(size_t)row * DIN])[t];
    float4 zv = ((const float4*)&zx[(size_t)row * DPROJ])[t];
    float g0 = yv.x * (zv.x / (1.f + expf(-zv.x)));
    float g1 = yv.y * (zv.y / (1.f + expf(-zv.y)));
    float g2 = yv.z * (zv.z / (1.f + expf(-zv.z)));
    float g3 = yv.w * (zv.w / (1.f + expf(-zv.w)));
    float ss = g0 * g0 + g1 * g1 + g2 * g2 + g3 * g3;
#pragma unroll
    for (int o = 16; o; o >>= 1) ss += __shfl_xor_sync(0xffffffffu, ss, o);
    __shared__ float red[8];
    if ((t & 31) == 0) red[t >> 5] = ss;
    __syncthreads();
    float tot = red[0] + red[1] + red[2] + red[3] + red[4] + red[5] + red[6] + red[7];
    float rms = rsqrtf(tot / (float)DIN + 1e-5f);
    float4 nw = ((const float4*)norm_w)[t];
    float4 o = make_float4(g0 * rms * nw.x, g1 * rms * nw.y, g2 * rms * nw.z, g3 * rms * nw.w);
    ((float4*)&y[(size_t)row * DIN])[t] = o;
}

// ---------------- launch ----------------
extern "C" void kernel_launch(void* const* d_in, const int* in_sizes, int n_in,
                              void* d_out, int out_size) {
    const float* x_seq      = (const float*)d_in[0];
    const float* in_proj_w  = (const float*)d_in[1];
    const float* conv_w     = (const float*)d_in[2];
    const float* conv_b     = (const float*)d_in[3];
    const float* dt_bias    = (const float*)d_in[4];
    const float* A_log      = (const float*)d_in[5];
    const float* Dv         = (const float*)d_in[6];
    const float* norm_w     = (const float*)d_in[7];
    const float* out_proj_w = (const float*)d_in[8];
    float* out = (float*)d_out;

    float *zx, *xbc, *xdt, *dtp, *acum, *states, *prefix, *y;
    cudaGetSymbolAddress((void**)&zx, g_zx);
    cudaGetSymbolAddress((void**)&xbc, g_xbc);
    cudaGetSymbolAddress((void**)&xdt, g_xdt);
    cudaGetSymbolAddress((void**)&dtp, g_dt);
    cudaGetSymbolAddress((void**)&acum, g_acum);
    cudaGetSymbolAddress((void**)&states, g_states);
    cudaGetSymbolAddress((void**)&prefix, g_prefix);
    cudaGetSymbolAddress((void**)&y, g_y);

    // 1. in_proj: zx[NTOK, 2192] = x_seq[NTOK,512] @ in_proj_w[2192,512]^T
    sgemm_nt<<<dim3((DPROJ + 63) / 64, NTOK / 128), 256>>>(x_seq, in_proj_w, zx, NTOK, DPROJ, DMODEL);
    // 2. causal conv + silu on xBC slice
    conv_kernel<<<(NTOK * CONVDIM) / 256, 256>>>(zx, conv_w, conv_b, xbc);
    // 3. dt softplus + per-chunk cumsum of dt*A
    dt_acum_kernel<<<dim3(B_SZ * NCH, NH), CHUNK>>>(zx, dt_bias, A_log, dtp, acum);
    // 4. xdt = xh * dt
    xdt_kernel<<<(NTOK * DIN) / 256, 256>>>(xbc, dtp, xdt);
    // 5. intra-chunk diagonal part
    ydiag_kernel<<<dim3(B_SZ * NCH, NH), 256>>>(xbc, xdt, acum, y);
    // 6. per-chunk states
    states_kernel<<<dim3(B_SZ * NCH, NH), 256>>>(xbc, xdt, acum, states);
    // 7. inter-chunk scan
    scan_kernel<<<dim3(B_SZ, NH), 256>>>(acum, states, prefix);
    // 8. off-diagonal contribution + D*xh
    yoff_kernel<<<dim3(B_SZ * NCH, NH), 256>>>(xbc, prefix, acum, Dv, y);
    // 9. gate + rmsnorm (in place on y)
    gate_norm_kernel<<<NTOK, 256>>>(zx, norm_w, y);
    // 10. out_proj: out[NTOK,512] = y[NTOK,1024] @ out_proj_w[512,1024]^T
    sgemm_nt<<<dim3(DMODEL / 64, NTOK / 128), 256>>>(y, out_proj_w, out, NTOK, DMODEL, DIN);
}

// round 2
// speedup vs baseline: 1.0802x; 1.0802x over previous
#include <cuda_runtime.h>
#include <math.h>
#include <stdint.h>

#define B_SZ   4
#define SEQ    4096
#define DMODEL 512
#define DIN    1024
#define NH     16
#define HD     64
#define DS     64
#define NCH    16
#define CHUNK  256
#define CONVDIM 1152
#define DPROJ  2192
#define NTOK   (B_SZ*SEQ)   // 16384

// ---------------- scratch (device globals; no runtime alloc) ----------------
__device__ float g_zx[(size_t)NTOK*DPROJ];        // in_proj output
__device__ float g_xbc[(size_t)NTOK*CONVDIM];     // conv+silu output
__device__ float g_dt[NTOK*NH];
__device__ float g_acum[B_SZ*NCH*NH*CHUNK];       // per-chunk inclusive cumsum of dt*A
__device__ float g_states[B_SZ*NCH*NH*HD*DS];     // per-chunk states [b,c,h,p,n]
__device__ float g_prefix[B_SZ*NCH*NH*HD*DS];     // inter-chunk prefix states
__device__ float g_y[(size_t)NTOK*DIN];           // y (diag, then +off, then gated/normed)

// ======================= tf32 MMA GEMM: C[M,N] = A[M,K] @ B[N,K]^T =======================
// 3xTF32 decomposition for ~fp32 accuracy. cp.async double-buffered, swizzled smem.
#define BM 128
#define BN 64
#define BK 32

__device__ __forceinline__ uint32_t cvt_tf32(float f) {
    uint32_t r; asm("cvt.rna.tf32.f32 %0, %1;" : "=r"(r) : "f"(f)); return r;
}
__device__ __forceinline__ void mma_tf32(float* c, const uint32_t* a, const uint32_t* b) {
    asm volatile("mma.sync.aligned.m16n8k8.row.col.f32.tf32.tf32.f32 "
        "{%0,%1,%2,%3}, {%4,%5,%6,%7}, {%8,%9}, {%0,%1,%2,%3};"
        : "+f"(c[0]), "+f"(c[1]), "+f"(c[2]), "+f"(c[3])
        : "r"(a[0]), "r"(a[1]), "r"(a[2]), "r"(a[3]), "r"(b[0]), "r"(b[1]));
}

// swizzled float index for element (row, k) in a [rows][32] tile
__device__ __forceinline__ int swz(int r, int k) {
    return r * 32 + ((((k >> 2) ^ (r & 7)) << 2) | (k & 3));
}

__global__ __launch_bounds__(256) void gemm_tf32(const float* __restrict__ A,
                                                 const float* __restrict__ Bw,
                                                 float* __restrict__ C,
                                                 int M, int N, int K) {
    __shared__ float As[2][BM * 32];
    __shared__ float Bs[2][BN * 32];
    int tid = threadIdx.x, lane = tid & 31, wid = tid >> 5;
    int wm = wid >> 1, wn = wid & 1;           // warp grid 4x2
    int g = lane >> 2, tg = lane & 3;
    int rowBase = blockIdx.y * BM, colBase = blockIdx.x * BN;

    float acc[2][4][4];
#pragma unroll
    for (int i = 0; i < 2; i++)
#pragma unroll
        for (int j = 0; j < 4; j++)
#pragma unroll
            for (int q = 0; q < 4; q++) acc[i][j][q] = 0.f;

    int KT = K / BK;

    // -------- tile loader (cp.async) --------
    auto loadTile = [&](int buf, int k0) {
#pragma unroll
        for (int q = 0; q < 4; q++) {                 // A: 128x32 = 1024 float4
            int idx = tid + q * 256;
            int r = idx >> 3, c4 = idx & 7;
            uint32_t dst = (uint32_t)__cvta_generic_to_shared(&As[buf][r * 32 + ((c4 ^ (r & 7)) << 2)]);
            const float* src = &A[(size_t)(rowBase + r) * K + k0 + c4 * 4];
            asm volatile("cp.async.ca.shared.global [%0], [%1], 16;" :: "r"(dst), "l"(src));
        }
#pragma unroll
        for (int q = 0; q < 2; q++) {                 // B: 64x32 = 512 float4
            int idx = tid + q * 256;
            int r = idx >> 3, c4 = idx & 7;
            int nrow = colBase + r;
            uint32_t dst = (uint32_t)__cvta_generic_to_shared(&Bs[buf][r * 32 + ((c4 ^ (r & 7)) << 2)]);
            const float* src = &Bw[(size_t)(nrow < N ? nrow : 0) * K + k0 + c4 * 4];
            int sz = (nrow < N) ? 16 : 0;
            asm volatile("cp.async.ca.shared.global [%0], [%1], 16, %2;" :: "r"(dst), "l"(src), "r"(sz));
        }
        asm volatile("cp.async.commit_group;");
    };

    loadTile(0, 0);
    for (int kt = 0; kt < KT; kt++) {
        if (kt + 1 < KT) {
            loadTile((kt + 1) & 1, (kt + 1) * BK);
            asm volatile("cp.async.wait_group 1;");
        } else {
            asm volatile("cp.async.wait_group 0;");
        }
        __syncthreads();
        const float* as = As[kt & 1];
        const float* bs = Bs[kt & 1];
#pragma unroll
        for (int k8 = 0; k8 < BK / 8; k8++) {
            int kb = k8 * 8;
            uint32_t ah[2][4], al[2][4];
#pragma unroll
            for (int tm = 0; tm < 2; tm++) {
                int m0 = wm * 32 + tm * 16;
                float f0 = as[swz(m0 + g,     kb + tg)];
                float f1 = as[swz(m0 + g + 8, kb + tg)];
                float f2 = as[swz(m0 + g,     kb + tg + 4)];
                float f3 = as[swz(m0 + g + 8, kb + tg + 4)];
                ah[tm][0] = cvt_tf32(f0); al[tm][0] = cvt_tf32(f0 - __uint_as_float(ah[tm][0]));
                ah[tm][1] = cvt_tf32(f1); al[tm][1] = cvt_tf32(f1 - __uint_as_float(ah[tm][1]));
                ah[tm][2] = cvt_tf32(f2); al[tm][2] = cvt_tf32(f2 - __uint_as_float(ah[tm][2]));
                ah[tm][3] = cvt_tf32(f3); al[tm][3] = cvt_tf32(f3 - __uint_as_float(ah[tm][3]));
            }
            uint32_t bh[4][2], bl[4][2];
#pragma unroll
            for (int tn = 0; tn < 4; tn++) {
                int n0 = wn * 32 + tn * 8;
                float f0 = bs[swz(n0 + g, kb + tg)];
                float f1 = bs[swz(n0 + g, kb + tg + 4)];
                bh[tn][0] = cvt_tf32(f0); bl[tn][0] = cvt_tf32(f0 - __uint_as_float(bh[tn][0]));
                bh[tn][1] = cvt_tf32(f1); bl[tn][1] = cvt_tf32(f1 - __uint_as_float(bh[tn][1]));
            }
#pragma unroll
            for (int tm = 0; tm < 2; tm++)
#pragma unroll
                for (int tn = 0; tn < 4; tn++) {
                    mma_tf32(acc[tm][tn], ah[tm], bh[tn]);
                    mma_tf32(acc[tm][tn], ah[tm], bl[tn]);
                    mma_tf32(acc[tm][tn], al[tm], bh[tn]);
                }
        }
        __syncthreads();
    }
    // epilogue
#pragma unroll
    for (int tm = 0; tm < 2; tm++) {
        int r0 = rowBase + wm * 32 + tm * 16;
#pragma unroll
        for (int tn = 0; tn < 4; tn++) {
            int c0 = colBase + wn * 32 + tn * 8 + tg * 2;
            if (c0 < N) {
                *(float2*)&C[(size_t)(r0 + g) * N + c0]     = make_float2(acc[tm][tn][0], acc[tm][tn][1]);
                *(float2*)&C[(size_t)(r0 + g + 8) * N + c0] = make_float2(acc[tm][tn][2], acc[tm][tn][3]);
            }
        }
    }
}

// ---------------- causal conv1d (width 4) + SiLU ----------------
__global__ __launch_bounds__(256) void conv_kernel(const float* __restrict__ zx,
                                                   const float* __restrict__ conv_w,
                                                   const float* __restrict__ conv_b,
                                                   float* __restrict__ xbc) {
    int idx = blockIdx.x * 256 + threadIdx.x;      // over NTOK*CONVDIM
    int c = idx % CONVDIM;
    int bl = idx / CONVDIM;
    int l = bl & (SEQ - 1);
    int b = bl >> 12;
    float acc = conv_b[c];
#pragma unroll
    for (int k = 0; k < 4; k++) {
        int ls = l - 3 + k;
        if (ls >= 0)
            acc += zx[(size_t)(b * SEQ + ls) * DPROJ + DIN + c] * conv_w[c * 4 + k];
    }
    xbc[idx] = acc / (1.f + __expf(-acc));   // silu
}

// ---------------- dt = softplus(raw + bias); a = dt*A; per-chunk inclusive cumsum ----------------
__global__ __launch_bounds__(256) void dt_acum_kernel(const float* __restrict__ zx,
                                                      const float* __restrict__ dt_bias,
                                                      const float* __restrict__ A_log,
                                                      float* __restrict__ dtp,
                                                      float* __restrict__ acum) {
    int bc = blockIdx.x;            // b*NCH + c
    int h = blockIdx.y;
    int b = bc >> 4, c = bc & 15;
    int l = threadIdx.x;
    int row = b * SEQ + c * CHUNK + l;
    float x = zx[(size_t)row * DPROJ + (DPROJ - NH) + h] + dt_bias[h];
    float dtv = (x > 20.f) ? x : log1pf(expf(x));
    dtp[row * NH + h] = dtv;
    float a = -expf(A_log[h]) * dtv;

    __shared__ float s[CHUNK];
    s[l] = a;
    __syncthreads();
#pragma unroll
    for (int off = 1; off < CHUNK; off <<= 1) {
        float v = (l >= off) ? s[l - off] : 0.f;
        __syncthreads();
        s[l] += v;
        __syncthreads();
    }
    acum[(bc * NH + h) * CHUNK + l] = s[l];
}

// ---------------- intra-chunk: Y_diag[l,p] = sum_{s<=l} (C_l.B_s) exp(ac_l-ac_s) (x*dt)[s,p] ----------------
__global__ __launch_bounds__(256) void ydiag_kernel(const float* __restrict__ xbc,
                                                    const float* __restrict__ dtp,
                                                    const float* __restrict__ acum,
                                                    float* __restrict__ y) {
    int bc = blockIdx.x, h = blockIdx.y;
    int b = bc >> 4, c = bc & 15;
    int l = threadIdx.x;
    int rowBase = b * SEQ + c * CHUNK;

    __shared__ float sAc[CHUNK];
    __shared__ float sB[64][64];
    __shared__ float sX[64][64];

    sAc[l] = acum[(bc * NH + h) * CHUNK + l];

    float creg[64];
    {
        const float4* crow = (const float4*)&xbc[(size_t)(rowBase + l) * CONVDIM + DIN + DS];
#pragma unroll
        for (int q = 0; q < 16; q++) {
            float4 v = crow[q];
            creg[q * 4 + 0] = v.x; creg[q * 4 + 1] = v.y;
            creg[q * 4 + 2] = v.z; creg[q * 4 + 3] = v.w;
        }
    }
    float acc[64];
#pragma unroll
    for (int p = 0; p < 64; p++) acc[p] = 0.f;

    __syncthreads();
    float aL = sAc[l];

    for (int st = 0; st < 4; st++) {
        // load 64 source rows of B and x*dt
#pragma unroll
        for (int q = 0; q < 4; q++) {
            int i = l + q * 256;           // float4 index 0..1023
            int r = i >> 4;                // row 0..63
            int nq = (i & 15) * 4;
            int srow = rowBase + st * 64 + r;
            *(float4*)&sB[r][nq] = *(const float4*)&xbc[(size_t)srow * CONVDIM + DIN + nq];
            float dtv = dtp[srow * NH + h];
            float4 xv = *(const float4*)&xbc[(size_t)srow * CONVDIM + h * HD + nq];
            xv.x *= dtv; xv.y *= dtv; xv.z *= dtv; xv.w *= dtv;
            *(float4*)&sX[r][nq] = xv;
        }
        __syncthreads();
        int smax = l - st * 64 + 1;        // count of valid ss in this tile
        if (smax > 64) smax = 64;
        for (int ss = 0; ss < smax; ss++) {
            float cb = 0.f;
#pragma unroll
            for (int n = 0; n < 64; n++) cb += creg[n] * sB[ss][n];
            float w = __expf(aL - sAc[st * 64 + ss]) * cb;
#pragma unroll
            for (int p = 0; p < 64; p++) acc[p] += w * sX[ss][p];
        }
        __syncthreads();
    }
    float* yout = &y[(size_t)(rowBase + l) * DIN + h * HD];
#pragma unroll
    for (int p = 0; p < 64; p += 4) {
        float4 v = make_float4(acc[p], acc[p + 1], acc[p + 2], acc[p + 3]);
        *(float4*)&yout[p] = v;
    }
}

// ---------------- per-chunk states[p,n] = sum_l exp(ac_end-ac_l) (x*dt)[l,p] B[l,n] ----------------
__global__ __launch_bounds__(256) void states_kernel(const float* __restrict__ xbc,
                                                     const float* __restrict__ dtp,
                                                     const float* __restrict__ acum,
                                                     float* __restrict__ states) {
    int bc = blockIdx.x, h = blockIdx.y;
    int b = bc >> 4, c = bc & 15;
    int t = threadIdx.x;
    int rowBase = b * SEQ + c * CHUNK;

    __shared__ float sDec[CHUNK];
    __shared__ float sB[64][64];
    __shared__ float sX[64][64];

    {
        float aEnd = acum[(bc * NH + h) * CHUNK + (CHUNK - 1)];
        sDec[t] = __expf(aEnd - acum[(bc * NH + h) * CHUNK + t]);
    }
    int p = t >> 2;
    int n0 = (t & 3) * 16;
    float acc[16];
#pragma unroll
    for (int j = 0; j < 16; j++) acc[j] = 0.f;
    __syncthreads();

    for (int st = 0; st < 4; st++) {
#pragma unroll
        for (int q = 0; q < 4; q++) {
            int i = t + q * 256;
            int r = i >> 4;
            int nq = (i & 15) * 4;
            int srow = rowBase + st * 64 + r;
            *(float4*)&sB[r][nq] = *(const float4*)&xbc[(size_t)srow * CONVDIM + DIN + nq];
            float dtv = dtp[srow * NH + h];
            float4 xv = *(const float4*)&xbc[(size_t)srow * CONVDIM + h * HD + nq];
            xv.x *= dtv; xv.y *= dtv; xv.z *= dtv; xv.w *= dtv;
            *(float4*)&sX[r][nq] = xv;
        }
        __syncthreads();
        for (int ss = 0; ss < 64; ss++) {
            float wx = sDec[st * 64 + ss] * sX[ss][p];
#pragma unroll
            for (int j = 0; j < 16; j++) acc[j] += wx * sB[ss][n0 + j];
        }
        __syncthreads();
    }
    float* out = &states[((size_t)(bc * NH + h)) * (HD * DS) + p * DS + n0];
#pragma unroll
    for (int j = 0; j < 16; j += 4) {
        float4 v = make_float4(acc[j], acc[j + 1], acc[j + 2], acc[j + 3]);
        *(float4*)&out[j] = v;
    }
}

// ---------------- inter-chunk sequential scan ----------------
__global__ __launch_bounds__(256) void scan_kernel(const float* __restrict__ acum,
                                                   const float* __restrict__ states,
                                                   float* __restrict__ prefix) {
    int b = blockIdx.x, h = blockIdx.y, t = threadIdx.x;
    float S[16];
#pragma unroll
    for (int j = 0; j < 16; j++) S[j] = 0.f;
    for (int c = 0; c < NCH; c++) {
        size_t base = ((size_t)((b * NCH + c) * NH + h)) * (HD * DS) + t * 16;
#pragma unroll
        for (int j = 0; j < 16; j += 4) {
            float4 v = make_float4(S[j], S[j + 1], S[j + 2], S[j + 3]);
            *(float4*)&prefix[base + j] = v;
        }
        float cs = __expf(acum[((b * NCH + c) * NH + h) * CHUNK + (CHUNK - 1)]);
#pragma unroll
        for (int j = 0; j < 16; j += 4) {
            float4 sv = *(const float4*)&states[base + j];
            S[j + 0] = cs * S[j + 0] + sv.x;
            S[j + 1] = cs * S[j + 1] + sv.y;
            S[j + 2] = cs * S[j + 2] + sv.z;
            S[j + 3] = cs * S[j + 3] + sv.w;
        }
    }
}

// ---------------- Y_off + D*xh combine ----------------
__global__ __launch_bounds__(256) void yoff_kernel(const float* __restrict__ xbc,
                                                   const float* __restrict__ prefix,
                                                   const float* __restrict__ acum,
                                                   const float* __restrict__ Dv,
                                                   float* __restrict__ y) {
    int bc = blockIdx.x, h = blockIdx.y;
    int b = bc >> 4, c = bc & 15;
    int l = threadIdx.x;
    int rowBase = b * SEQ + c * CHUNK;

    __shared__ float sP[HD * DS];   // 4096 floats
    {
        const float4* src = (const float4*)&prefix[((size_t)(bc * NH + h)) * (HD * DS)];
#pragma unroll
        for (int q = 0; q < 4; q++) ((float4*)sP)[l + q * 256] = src[l + q * 256];
    }
    float creg[64];
    {
        const float4* crow = (const float4*)&xbc[(size_t)(rowBase + l) * CONVDIM + DIN + DS];
#pragma unroll
        for (int q = 0; q < 16; q++) {
            float4 v = crow[q];
            creg[q * 4 + 0] = v.x; creg[q * 4 + 1] = v.y;
            creg[q * 4 + 2] = v.z; creg[q * 4 + 3] = v.w;
        }
    }
    float aE = __expf(acum[(bc * NH + h) * CHUNK + l]);
    float Dh = Dv[h];
    __syncthreads();

    const float4* xh4 = (const float4*)&xbc[(size_t)(rowBase + l) * CONVDIM + h * HD];
    float4* y4 = (float4*)&y[(size_t)(rowBase + l) * DIN + h * HD];
#pragma unroll
    for (int p0 = 0; p0 < 64; p0 += 4) {
        float4 xh = xh4[p0 / 4];
        float4 yd = y4[p0 / 4];
        float o[4];
#pragma unroll
        for (int i = 0; i < 4; i++) {
            float s = 0.f;
#pragma unroll
            for (int n = 0; n < 64; n++) s += creg[n] * sP[(p0 + i) * DS + n];
            float xv = (i == 0) ? xh.x : (i == 1) ? xh.y : (i == 2) ? xh.z : xh.w;
            float dv = (i == 0) ? yd.x : (i == 1) ? yd.y : (i == 2) ? yd.z : yd.w;
            o[i] = dv + aE * s + Dh * xv;
        }
        y4[p0 / 4] = make_float4(o[0], o[1], o[2], o[3]);
    }
}

// ---------------- gate with silu(z) + RMSNorm ----------------
__global__ __launch_bounds__(256) void gate_norm_kernel(const float* __restrict__ zx,
                                                        const float* __restrict__ norm_w,
                                                        float* __restrict__ y) {
    int row = blockIdx.x;
    int t = threadIdx.x;
    float4 yv = ((const float4*)&y[(size_t)row * DIN])[t];
    float4 zv = ((const float4*)&zx[(size_t)row * DPROJ])[t];
    float g0 = yv.x * (zv.x / (1.f + __expf(-zv.x)));
    float g1 = yv.y * (zv.y / (1.f + __expf(-zv.y)));
    float g2 = yv.z * (zv.z / (1.f + __expf(-zv.z)));
    float g3 = yv.w * (zv.w / (1.f + __expf(-zv.w)));
    float ss = g0 * g0 + g1 * g1 + g2 * g2 + g3 * g3;
#pragma unroll
    for (int o = 16; o; o >>= 1) ss += __shfl_xor_sync(0xffffffffu, ss, o);
    __shared__ float red[8];
    if ((t & 31) == 0) red[t >> 5] = ss;
    __syncthreads();
    float tot = red[0] + red[1] + red[2] + red[3] + red[4] + red[5] + red[6] + red[7];
    float rms = rsqrtf(tot / (float)DIN + 1e-5f);
    float4 nw = ((const float4*)norm_w)[t];
    float4 o = make_float4(g0 * rms * nw.x, g1 * rms * nw.y, g2 * rms * nw.z, g3 * rms * nw.w);
    ((float4*)&y[(size_t)row * DIN])[t] = o;
}

// ---------------- launch ----------------
extern "C" void kernel_launch(void* const* d_in, const int* in_sizes, int n_in,
                              void* d_out, int out_size) {
    const float* x_seq      = (const float*)d_in[0];
    const float* in_proj_w  = (const float*)d_in[1];
    const float* conv_w     = (const float*)d_in[2];
    const float* conv_b     = (const float*)d_in[3];
    const float* dt_bias    = (const float*)d_in[4];
    const float* A_log      = (const float*)d_in[5];
    const float* Dv         = (const float*)d_in[6];
    const float* norm_w     = (const float*)d_in[7];
    const float* out_proj_w = (const float*)d_in[8];
    float* out = (float*)d_out;

    float *zx, *xbc, *dtp, *acum, *states, *prefix, *y;
    cudaGetSymbolAddress((void**)&zx, g_zx);
    cudaGetSymbolAddress((void**)&xbc, g_xbc);
    cudaGetSymbolAddress((void**)&dtp, g_dt);
    cudaGetSymbolAddress((void**)&acum, g_acum);
    cudaGetSymbolAddress((void**)&states, g_states);
    cudaGetSymbolAddress((void**)&prefix, g_prefix);
    cudaGetSymbolAddress((void**)&y, g_y);

    // 1. in_proj: zx[NTOK, 2192] = x_seq[NTOK,512] @ in_proj_w[2192,512]^T
    gemm_tf32<<<dim3((DPROJ + BN - 1) / BN, NTOK / BM), 256>>>(x_seq, in_proj_w, zx, NTOK, DPROJ, DMODEL);
    // 2. causal conv + silu on xBC slice
    conv_kernel<<<(NTOK * CONVDIM) / 256, 256>>>(zx, conv_w, conv_b, xbc);
    // 3. dt softplus + per-chunk cumsum of dt*A
    dt_acum_kernel<<<dim3(B_SZ * NCH, NH), CHUNK>>>(zx, dt_bias, A_log, dtp, acum);
    // 4. intra-chunk diagonal part (x*dt folded into loader)
    ydiag_kernel<<<dim3(B_SZ * NCH, NH), 256>>>(xbc, dtp, acum, y);
    // 5. per-chunk states
    states_kernel<<<dim3(B_SZ * NCH, NH), 256>>>(xbc, dtp, acum, states);
    // 6. inter-chunk scan
    scan_kernel<<<dim3(B_SZ, NH), 256>>>(acum, states, prefix);
    // 7. off-diagonal contribution + D*xh
    yoff_kernel<<<dim3(B_SZ * NCH, NH), 256>>>(xbc, prefix, acum, Dv, y);
    // 8. gate + rmsnorm (in place on y)
    gate_norm_kernel<<<NTOK, 256>>>(zx, norm_w, y);
    // 9. out_proj: out[NTOK,512] = y[NTOK,1024] @ out_proj_w[512,1024]^T
    gemm_tf32<<<dim3(DMODEL / BN, NTOK / BM), 256>>>(y, out_proj_w, out, NTOK, DMODEL, DIN);
}

// round 7
// speedup vs baseline: 1.5943x; 1.4759x over previous
#include <cuda_runtime.h>
#include <math.h>
#include <stdint.h>

#define B_SZ   4
#define SEQ    4096
#define DMODEL 512
#define DIN    1024
#define NH     16
#define HD     64
#define DS     64
#define NCH    16
#define CHUNK  256
#define CONVDIM 1152
#define DPROJ  2192
#define NTOK   (B_SZ*SEQ)   // 16384

// ---------------- scratch (device globals; no runtime alloc) ----------------
__device__ float g_zx[(size_t)NTOK*DPROJ];
__device__ float g_xbc[(size_t)NTOK*CONVDIM];
__device__ float g_dt[NTOK*NH];
__device__ float g_acum[B_SZ*NCH*NH*CHUNK];
__device__ float g_states[B_SZ*NCH*NH*HD*DS];
__device__ float g_prefix[B_SZ*NCH*NH*HD*DS];
__device__ float g_y[(size_t)NTOK*DIN];

// ---------------- tf32 helpers ----------------
__device__ __forceinline__ uint32_t cvt_tf32(float f) {
    uint32_t r; asm("cvt.rna.tf32.f32 %0, %1;" : "=r"(r) : "f"(f)); return r;
}
__device__ __forceinline__ float tf32r(float f) { return __uint_as_float(cvt_tf32(f)); }

__device__ __forceinline__ void mma_tf32(float* c, const uint32_t* a, const uint32_t* b) {
    asm volatile("mma.sync.aligned.m16n8k8.row.col.f32.tf32.tf32.f32 "
        "{%0,%1,%2,%3}, {%4,%5,%6,%7}, {%8,%9}, {%0,%1,%2,%3};"
        : "+f"(c[0]), "+f"(c[1]), "+f"(c[2]), "+f"(c[3])
        : "r"(a[0]), "r"(a[1]), "r"(a[2]), "r"(a[3]), "r"(b[0]), "r"(b[1]));
}
__device__ __forceinline__ void mma8(float* c, const float* a, const float* b) {
    asm volatile("mma.sync.aligned.m16n8k8.row.col.f32.tf32.tf32.f32 "
        "{%0,%1,%2,%3}, {%4,%5,%6,%7}, {%8,%9}, {%0,%1,%2,%3};"
        : "+f"(c[0]), "+f"(c[1]), "+f"(c[2]), "+f"(c[3])
        : "r"(__float_as_uint(a[0])), "r"(__float_as_uint(a[1])),
          "r"(__float_as_uint(a[2])), "r"(__float_as_uint(a[3])),
          "r"(__float_as_uint(b[0])), "r"(__float_as_uint(b[1])));
}

// swizzled index into a [64][64] tile: element (r, c)
__device__ __forceinline__ int sw64(int r, int c) {
    return r * 64 + ((((c >> 2) ^ (r & 7)) << 2) | (c & 3));
}

// ======================= tf32 MMA GEMM (3xTF32) =======================
#define BM 128
#define BN 64
#define BK 32

__device__ __forceinline__ int swz(int r, int k) {
    return r * 32 + ((((k >> 2) ^ (r & 7)) << 2) | (k & 3));
}

__global__ __launch_bounds__(256) void gemm_tf32(const float* __restrict__ A,
                                                 const float* __restrict__ Bw,
                                                 float* __restrict__ C,
                                                 int M, int N, int K) {
    __shared__ float As[2][BM * 32];
    __shared__ float Bs[2][BN * 32];
    int tid = threadIdx.x, lane = tid & 31, wid = tid >> 5;
    int wm = wid >> 1, wn = wid & 1;
    int g = lane >> 2, tg = lane & 3;
    int rowBase = blockIdx.y * BM, colBase = blockIdx.x * BN;

    float acc[2][4][4];
#pragma unroll
    for (int i = 0; i < 2; i++)
#pragma unroll
        for (int j = 0; j < 4; j++)
#pragma unroll
            for (int q = 0; q < 4; q++) acc[i][j][q] = 0.f;

    int KT = K / BK;
    auto loadTile = [&](int buf, int k0) {
#pragma unroll
        for (int q = 0; q < 4; q++) {
            int idx = tid + q * 256;
            int r = idx >> 3, c4 = idx & 7;
            uint32_t dst = (uint32_t)__cvta_generic_to_shared(&As[buf][r * 32 + ((c4 ^ (r & 7)) << 2)]);
            const float* src = &A[(size_t)(rowBase + r) * K + k0 + c4 * 4];
            asm volatile("cp.async.ca.shared.global [%0], [%1], 16;" :: "r"(dst), "l"(src));
        }
#pragma unroll
        for (int q = 0; q < 2; q++) {
            int idx = tid + q * 256;
            int r = idx >> 3, c4 = idx & 7;
            int nrow = colBase + r;
            uint32_t dst = (uint32_t)__cvta_generic_to_shared(&Bs[buf][r * 32 + ((c4 ^ (r & 7)) << 2)]);
            const float* src = &Bw[(size_t)(nrow < N ? nrow : 0) * K + k0 + c4 * 4];
            int sz = (nrow < N) ? 16 : 0;
            asm volatile("cp.async.ca.shared.global [%0], [%1], 16, %2;" :: "r"(dst), "l"(src), "r"(sz));
        }
        asm volatile("cp.async.commit_group;");
    };

    loadTile(0, 0);
    for (int kt = 0; kt < KT; kt++) {
        if (kt + 1 < KT) {
            loadTile((kt + 1) & 1, (kt + 1) * BK);
            asm volatile("cp.async.wait_group 1;");
        } else {
            asm volatile("cp.async.wait_group 0;");
        }
        __syncthreads();
        const float* as = As[kt & 1];
        const float* bs = Bs[kt & 1];
#pragma unroll
        for (int k8 = 0; k8 < BK / 8; k8++) {
            int kb = k8 * 8;
            uint32_t ah[2][4], al[2][4];
#pragma unroll
            for (int tm = 0; tm < 2; tm++) {
                int m0 = wm * 32 + tm * 16;
                float f0 = as[swz(m0 + g,     kb + tg)];
                float f1 = as[swz(m0 + g + 8, kb + tg)];
                float f2 = as[swz(m0 + g,     kb + tg + 4)];
                float f3 = as[swz(m0 + g + 8, kb + tg + 4)];
                ah[tm][0] = cvt_tf32(f0); al[tm][0] = cvt_tf32(f0 - __uint_as_float(ah[tm][0]));
                ah[tm][1] = cvt_tf32(f1); al[tm][1] = cvt_tf32(f1 - __uint_as_float(ah[tm][1]));
                ah[tm][2] = cvt_tf32(f2); al[tm][2] = cvt_tf32(f2 - __uint_as_float(ah[tm][2]));
                ah[tm][3] = cvt_tf32(f3); al[tm][3] = cvt_tf32(f3 - __uint_as_float(ah[tm][3]));
            }
            uint32_t bh[4][2], bl[4][2];
#pragma unroll
            for (int tn = 0; tn < 4; tn++) {
                int n0 = wn * 32 + tn * 8;
                float f0 = bs[swz(n0 + g, kb + tg)];
                float f1 = bs[swz(n0 + g, kb + tg + 4)];
                bh[tn][0] = cvt_tf32(f0); bl[tn][0] = cvt_tf32(f0 - __uint_as_float(bh[tn][0]));
                bh[tn][1] = cvt_tf32(f1); bl[tn][1] = cvt_tf32(f1 - __uint_as_float(bh[tn][1]));
            }
#pragma unroll
            for (int tm = 0; tm < 2; tm++)
#pragma unroll
                for (int tn = 0; tn < 4; tn++) {
                    mma_tf32(acc[tm][tn], ah[tm], bh[tn]);
                    mma_tf32(acc[tm][tn], ah[tm], bl[tn]);
                    mma_tf32(acc[tm][tn], al[tm], bh[tn]);
                }
        }
        __syncthreads();
    }
#pragma unroll
    for (int tm = 0; tm < 2; tm++) {
        int r0 = rowBase + wm * 32 + tm * 16;
#pragma unroll
        for (int tn = 0; tn < 4; tn++) {
            int c0 = colBase + wn * 32 + tn * 8 + tg * 2;
            if (c0 < N) {
                *(float2*)&C[(size_t)(r0 + g) * N + c0]     = make_float2(acc[tm][tn][0], acc[tm][tn][1]);
                *(float2*)&C[(size_t)(r0 + g + 8) * N + c0] = make_float2(acc[tm][tn][2], acc[tm][tn][3]);
            }
        }
    }
}

// ---------------- causal conv1d (width 4) + SiLU ----------------
__global__ __launch_bounds__(256) void conv_kernel(const float* __restrict__ zx,
                                                   const float* __restrict__ conv_w,
                                                   const float* __restrict__ conv_b,
                                                   float* __restrict__ xbc) {
    int idx = blockIdx.x * 256 + threadIdx.x;
    int c = idx % CONVDIM;
    int bl = idx / CONVDIM;
    int l = bl & (SEQ - 1);
    int b = bl >> 12;
    float acc = conv_b[c];
#pragma unroll
    for (int k = 0; k < 4; k++) {
        int ls = l - 3 + k;
        if (ls >= 0)
            acc += zx[(size_t)(b * SEQ + ls) * DPROJ + DIN + c] * conv_w[c * 4 + k];
    }
    xbc[idx] = acc / (1.f + __expf(-acc));
}

// ---------------- dt softplus + per-chunk cumsum of dt*A ----------------
__global__ __launch_bounds__(256) void dt_acum_kernel(const float* __restrict__ zx,
                                                      const float* __restrict__ dt_bias,
                                                      const float* __restrict__ A_log,
                                                      float* __restrict__ dtp,
                                                      float* __restrict__ acum) {
    int bc = blockIdx.x;
    int h = blockIdx.y;
    int b = bc >> 4, c = bc & 15;
    int l = threadIdx.x;
    int row = b * SEQ + c * CHUNK + l;
    float x = zx[(size_t)row * DPROJ + (DPROJ - NH) + h] + dt_bias[h];
    float dtv = (x > 20.f) ? x : log1pf(expf(x));
    dtp[row * NH + h] = dtv;
    float a = -expf(A_log[h]) * dtv;

    __shared__ float s[CHUNK];
    s[l] = a;
    __syncthreads();
#pragma unroll
    for (int off = 1; off < CHUNK; off <<= 1) {
        float v = (l >= off) ? s[l - off] : 0.f;
        __syncthreads();
        s[l] += v;
        __syncthreads();
    }
    acum[(bc * NH + h) * CHUNK + l] = s[l];
}

// =================== MMA intra-chunk Y_diag, 64x64 tiles ===================
// dynamic smem = EXACTLY 49152 bytes (3 x 16KB), ZERO static smem.
__global__ __launch_bounds__(128) void ydiag_mma(const float* __restrict__ xbc,
                                                 const float* __restrict__ dtp,
                                                 const float* __restrict__ acum,
                                                 float* __restrict__ y) {
    extern __shared__ float sm[];
    float* sB = sm;            // [64][64] swizzled, tf32 B rows
    float* sX = sm + 4096;     // [64][64] swizzled, tf32 (x*dt)
    float* sS = sm + 8192;     // [64][64] swizzled, tf32 masked S (warp-private rows)

    int bc = blockIdx.x, h = blockIdx.y, lt = blockIdx.z;
    int b = bc >> 4, c = bc & 15;
    int rowBase = b * SEQ + c * CHUNK;
    int tid = threadIdx.x, lane = tid & 31, w = tid >> 5;
    int g = lane >> 2, tg = lane & 3;
    int lbase = lt * 64;
    const float* acbase = &acum[(bc * NH + h) * CHUNK];

    // C fragments in registers (rows w*16+g, w*16+g+8 of this l-tile)
    float creg[8][4];
    {
        const float* c0 = &xbc[(size_t)(rowBase + lbase + w * 16 + g) * CONVDIM + DIN + DS];
        const float* c1 = &xbc[(size_t)(rowBase + lbase + w * 16 + g + 8) * CONVDIM + DIN + DS];
#pragma unroll
        for (int kb8 = 0; kb8 < 8; kb8++) {
            int kb = kb8 * 8;
            creg[kb8][0] = tf32r(c0[kb + tg]);
            creg[kb8][1] = tf32r(c1[kb + tg]);
            creg[kb8][2] = tf32r(c0[kb + tg + 4]);
            creg[kb8][3] = tf32r(c1[kb + tg + 4]);
        }
    }
    float aL0 = acbase[lbase + w * 16 + g];
    float aL1 = acbase[lbase + w * 16 + g + 8];
    int lg0 = lbase + w * 16 + g, lg1 = lg0 + 8;

    float accY[8][4];
#pragma unroll
    for (int nt = 0; nt < 8; nt++)
#pragma unroll
        for (int q = 0; q < 4; q++) accY[nt][q] = 0.f;

    for (int st = 0; st <= lt; st++) {
        __syncthreads();
        int sbase = st * 64;
        for (int i = tid; i < 64 * 16; i += 128) {
            int r = i >> 4, q = (i & 15) * 4;
            size_t grow = (size_t)(rowBase + sbase + r);
            float4 bv = *(const float4*)&xbc[grow * CONVDIM + DIN + q];
            float4 bt = make_float4(tf32r(bv.x), tf32r(bv.y), tf32r(bv.z), tf32r(bv.w));
            *(float4*)&sB[r * 64 + ((((q >> 2) ^ (r & 7)) << 2))] = bt;
            float dtv = dtp[grow * NH + h];
            float4 xv = *(const float4*)&xbc[grow * CONVDIM + h * HD + q];
            float4 xt = make_float4(tf32r(xv.x * dtv), tf32r(xv.y * dtv),
                                    tf32r(xv.z * dtv), tf32r(xv.w * dtv));
            *(float4*)&sX[r * 64 + ((((q >> 2) ^ (r & 7)) << 2))] = xt;
        }
        __syncthreads();

        // stage 1: S = C @ B^T   (64x64x64)
        float accS[8][4];
#pragma unroll
        for (int nt = 0; nt < 8; nt++)
#pragma unroll
            for (int q = 0; q < 4; q++) accS[nt][q] = 0.f;
#pragma unroll
        for (int kb8 = 0; kb8 < 8; kb8++) {
            int kb = kb8 * 8;
#pragma unroll
            for (int nt = 0; nt < 8; nt++) {
                float bf[2] = { sB[sw64(nt * 8 + g, kb + tg)],
                                sB[sw64(nt * 8 + g, kb + tg + 4)] };
                mma8(accS[nt], creg[kb8], bf);
            }
        }
        // mask + decay -> warp-private sS rows (tf32); acum values from gmem (L1-hot)
#pragma unroll
        for (int nt = 0; nt < 8; nt++) {
            int col0 = nt * 8 + 2 * tg;
            int s0 = sbase + col0, s1 = s0 + 1;
            float as0 = __ldg(&acbase[s0]), as1 = __ldg(&acbase[s1]);
            float w00 = (s0 <= lg0) ? __expf(aL0 - as0) : 0.f;
            float w01 = (s1 <= lg0) ? __expf(aL0 - as1) : 0.f;
            float w10 = (s0 <= lg1) ? __expf(aL1 - as0) : 0.f;
            float w11 = (s1 <= lg1) ? __expf(aL1 - as1) : 0.f;
            *(float2*)&sS[sw64(w * 16 + g, col0)] =
                make_float2(tf32r(accS[nt][0] * w00), tf32r(accS[nt][1] * w01));
            *(float2*)&sS[sw64(w * 16 + g + 8, col0)] =
                make_float2(tf32r(accS[nt][2] * w10), tf32r(accS[nt][3] * w11));
        }
        __syncwarp();

        // stage 2: Y += S @ X   (64x64x64)
#pragma unroll
        for (int kb8 = 0; kb8 < 8; kb8++) {
            int kb = kb8 * 8;
            float a[4];
            a[0] = sS[sw64(w * 16 + g, kb + tg)];
            a[1] = sS[sw64(w * 16 + g + 8, kb + tg)];
            a[2] = sS[sw64(w * 16 + g, kb + tg + 4)];
            a[3] = sS[sw64(w * 16 + g + 8, kb + tg + 4)];
#pragma unroll
            for (int nt = 0; nt < 8; nt++) {
                float bf[2] = { sX[sw64(kb + tg, nt * 8 + g)],
                                sX[sw64(kb + tg + 4, nt * 8 + g)] };
                mma8(accY[nt], a, bf);
            }
        }
    }
    size_t r0 = (size_t)(rowBase + lbase + w * 16 + g);
#pragma unroll
    for (int nt = 0; nt < 8; nt++) {
        int col = h * HD + nt * 8 + 2 * tg;
        *(float2*)&y[r0 * DIN + col]       = make_float2(accY[nt][0], accY[nt][1]);
        *(float2*)&y[(r0 + 8) * DIN + col] = make_float2(accY[nt][2], accY[nt][3]);
    }
}

// =================== MMA per-chunk states: 32KB static smem ===================
__global__ __launch_bounds__(128) void states_mma(const float* __restrict__ xbc,
                                                  const float* __restrict__ dtp,
                                                  const float* __restrict__ acum,
                                                  float* __restrict__ states) {
    __shared__ float sX[4096];   // [64][64] swizzled (dec * x * dt)
    __shared__ float sB[4096];   // [64][64] swizzled

    int bc = blockIdx.x, h = blockIdx.y;
    int b = bc >> 4, c = bc & 15;
    int rowBase = b * SEQ + c * CHUNK;
    int tid = threadIdx.x, lane = tid & 31, w = tid >> 5;
    int g = lane >> 2, tg = lane & 3;
    int m0 = w * 16;
    const float* acbase = &acum[(bc * NH + h) * CHUNK];
    float aEnd = acbase[CHUNK - 1];

    float acc[8][4];
#pragma unroll
    for (int nt = 0; nt < 8; nt++)
#pragma unroll
        for (int q = 0; q < 4; q++) acc[nt][q] = 0.f;

    for (int st = 0; st < 4; st++) {
        __syncthreads();
        int sbase = st * 64;
        for (int i = tid; i < 64 * 16; i += 128) {
            int r = i >> 4, q = (i & 15) * 4;
            size_t grow = (size_t)(rowBase + sbase + r);
            float dec = __expf(aEnd - acbase[sbase + r]);
            float dtv = dtp[grow * NH + h] * dec;
            float4 xv = *(const float4*)&xbc[grow * CONVDIM + h * HD + q];
            float4 xt = make_float4(tf32r(xv.x * dtv), tf32r(xv.y * dtv),
                                    tf32r(xv.z * dtv), tf32r(xv.w * dtv));
            *(float4*)&sX[r * 64 + ((((q >> 2) ^ (r & 7)) << 2))] = xt;
            float4 bv = *(const float4*)&xbc[grow * CONVDIM + DIN + q];
            float4 bt = make_float4(tf32r(bv.x), tf32r(bv.y), tf32r(bv.z), tf32r(bv.w));
            *(float4*)&sB[r * 64 + ((((q >> 2) ^ (r & 7)) << 2))] = bt;
        }
        __syncthreads();
#pragma unroll
        for (int kb8 = 0; kb8 < 8; kb8++) {
            int kb = kb8 * 8;
            float a[4];
            a[0] = sX[sw64(kb + tg, m0 + g)];
            a[1] = sX[sw64(kb + tg, m0 + g + 8)];
            a[2] = sX[sw64(kb + tg + 4, m0 + g)];
            a[3] = sX[sw64(kb + tg + 4, m0 + g + 8)];
#pragma unroll
            for (int nt = 0; nt < 8; nt++) {
                float bf[2] = { sB[sw64(nt * 8 + g, kb + tg)],
                                sB[sw64(nt * 8 + g, kb + tg + 4)] };
                mma8(acc[nt], a, bf);
            }
        }
    }
    size_t base = (size_t)(bc * NH + h) * (HD * DS);
#pragma unroll
    for (int nt = 0; nt < 8; nt++) {
        int col = nt * 8 + 2 * tg;
        *(float2*)&states[base + (m0 + g) * DS + col]     = make_float2(acc[nt][0], acc[nt][1]);
        *(float2*)&states[base + (m0 + g + 8) * DS + col] = make_float2(acc[nt][2], acc[nt][3]);
    }
}

// ---------------- inter-chunk sequential scan ----------------
__global__ __launch_bounds__(256) void scan_kernel(const float* __restrict__ acum,
                                                   const float* __restrict__ states,
                                                   float* __restrict__ prefix) {
    int b = blockIdx.x, h = blockIdx.y, t = threadIdx.x;
    float S[16];
#pragma unroll
    for (int j = 0; j < 16; j++) S[j] = 0.f;
    for (int c = 0; c < NCH; c++) {
        size_t base = ((size_t)((b * NCH + c) * NH + h)) * (HD * DS) + t * 16;
#pragma unroll
        for (int j = 0; j < 16; j += 4) {
            float4 v = make_float4(S[j], S[j + 1], S[j + 2], S[j + 3]);
            *(float4*)&prefix[base + j] = v;
        }
        float cs = __expf(acum[((b * NCH + c) * NH + h) * CHUNK + (CHUNK - 1)]);
#pragma unroll
        for (int j = 0; j < 16; j += 4) {
            float4 sv = *(const float4*)&states[base + j];
            S[j + 0] = cs * S[j + 0] + sv.x;
            S[j + 1] = cs * S[j + 1] + sv.y;
            S[j + 2] = cs * S[j + 2] + sv.z;
            S[j + 3] = cs * S[j + 3] + sv.w;
        }
    }
}

// =================== MMA Y_off + D*xh: 16KB static smem, C-frags in registers ===================
__global__ __launch_bounds__(128) void yoff_mma(const float* __restrict__ xbc,
                                                const float* __restrict__ prefix,
                                                const float* __restrict__ acum,
                                                const float* __restrict__ Dv,
                                                float* __restrict__ y) {
    __shared__ float sP[4096];   // [64][64] swizzled, rows = p, cols = n

    int bc = blockIdx.x, h = blockIdx.y, lt = blockIdx.z;
    int b = bc >> 4, c = bc & 15;
    int rowBase = b * SEQ + c * CHUNK;
    int tid = threadIdx.x, lane = tid & 31, w = tid >> 5;
    int g = lane >> 2, tg = lane & 3;
    int lbase = lt * 64;

    size_t pbase = (size_t)(bc * NH + h) * (HD * DS);
    for (int i = tid; i < 64 * 16; i += 128) {
        int r = i >> 4, q = (i & 15) * 4;
        float4 v = *(const float4*)&prefix[pbase + r * DS + q];
        float4 vt = make_float4(tf32r(v.x), tf32r(v.y), tf32r(v.z), tf32r(v.w));
        *(float4*)&sP[r * 64 + ((((q >> 2) ^ (r & 7)) << 2))] = vt;
    }

    float creg[8][4];
    {
        const float* c0 = &xbc[(size_t)(rowBase + lbase + w * 16 + g) * CONVDIM + DIN + DS];
        const float* c1 = &xbc[(size_t)(rowBase + lbase + w * 16 + g + 8) * CONVDIM + DIN + DS];
#pragma unroll
        for (int kb8 = 0; kb8 < 8; kb8++) {
            int kb = kb8 * 8;
            creg[kb8][0] = tf32r(c0[kb + tg]);
            creg[kb8][1] = tf32r(c1[kb + tg]);
            creg[kb8][2] = tf32r(c0[kb + tg + 4]);
            creg[kb8][3] = tf32r(c1[kb + tg + 4]);
        }
    }
    __syncthreads();

    float acc[8][4];
#pragma unroll
    for (int nt = 0; nt < 8; nt++)
#pragma unroll
        for (int q = 0; q < 4; q++) acc[nt][q] = 0.f;

#pragma unroll
    for (int kb8 = 0; kb8 < 8; kb8++) {
        int kb = kb8 * 8;
#pragma unroll
        for (int nt = 0; nt < 8; nt++) {
            float bf[2] = { sP[sw64(nt * 8 + g, kb + tg)],
                            sP[sw64(nt * 8 + g, kb + tg + 4)] };
            mma8(acc[nt], creg[kb8], bf);
        }
    }

    float Dh = Dv[h];
    float ae0 = __expf(acum[(bc * NH + h) * CHUNK + lbase + w * 16 + g]);
    float ae1 = __expf(acum[(bc * NH + h) * CHUNK + lbase + w * 16 + g + 8]);
    size_t grow = (size_t)(rowBase + lbase + w * 16 + g);
#pragma unroll
    for (int nt = 0; nt < 8; nt++) {
        int col = h * HD + nt * 8 + 2 * tg;
        float2 yv0 = *(float2*)&y[grow * DIN + col];
        float2 xh0 = *(const float2*)&xbc[grow * CONVDIM + col];
        float2 yv1 = *(float2*)&y[(grow + 8) * DIN + col];
        float2 xh1 = *(const float2*)&xbc[(grow + 8) * CONVDIM + col];
        yv0.x += ae0 * acc[nt][0] + Dh * xh0.x;
        yv0.y += ae0 * acc[nt][1] + Dh * xh0.y;
        yv1.x += ae1 * acc[nt][2] + Dh * xh1.x;
        yv1.y += ae1 * acc[nt][3] + Dh * xh1.y;
        *(float2*)&y[grow * DIN + col] = yv0;
        *(float2*)&y[(grow + 8) * DIN + col] = yv1;
    }
}

// ---------------- gate with silu(z) + RMSNorm ----------------
__global__ __launch_bounds__(256) void gate_norm_kernel(const float* __restrict__ zx,
                                                        const float* __restrict__ norm_w,
                                                        float* __restrict__ y) {
    int row = blockIdx.x;
    int t = threadIdx.x;
    float4 yv = ((const float4*)&y[(size_t)row * DIN])[t];
    float4 zv = ((const float4*)&zx[(size_t)row * DPROJ])[t];
    float g0 = yv.x * (zv.x / (1.f + __expf(-zv.x)));
    float g1 = yv.y * (zv.y / (1.f + __expf(-zv.y)));
    float g2 = yv.z * (zv.z / (1.f + __expf(-zv.z)));
    float g3 = yv.w * (zv.w / (1.f + __expf(-zv.w)));
    float ss = g0 * g0 + g1 * g1 + g2 * g2 + g3 * g3;
#pragma unroll
    for (int o = 16; o; o >>= 1) ss += __shfl_xor_sync(0xffffffffu, ss, o);
    __shared__ float red[8];
    if ((t & 31) == 0) red[t >> 5] = ss;
    __syncthreads();
    float tot = red[0] + red[1] + red[2] + red[3] + red[4] + red[5] + red[6] + red[7];
    float rms = rsqrtf(tot / (float)DIN + 1e-5f);
    float4 nw = ((const float4*)norm_w)[t];
    float4 o = make_float4(g0 * rms * nw.x, g1 * rms * nw.y, g2 * rms * nw.z, g3 * rms * nw.w);
    ((float4*)&y[(size_t)row * DIN])[t] = o;
}

// ---------------- launch ----------------
extern "C" void kernel_launch(void* const* d_in, const int* in_sizes, int n_in,
                              void* d_out, int out_size) {
    const float* x_seq      = (const float*)d_in[0];
    const float* in_proj_w  = (const float*)d_in[1];
    const float* conv_w     = (const float*)d_in[2];
    const float* conv_b     = (const float*)d_in[3];
    const float* dt_bias    = (const float*)d_in[4];
    const float* A_log      = (const float*)d_in[5];
    const float* Dv         = (const float*)d_in[6];
    const float* norm_w     = (const float*)d_in[7];
    const float* out_proj_w = (const float*)d_in[8];
    float* out = (float*)d_out;

    float *zx, *xbc, *dtp, *acum, *states, *prefix, *y;
    cudaGetSymbolAddress((void**)&zx, g_zx);
    cudaGetSymbolAddress((void**)&xbc, g_xbc);
    cudaGetSymbolAddress((void**)&dtp, g_dt);
    cudaGetSymbolAddress((void**)&acum, g_acum);
    cudaGetSymbolAddress((void**)&states, g_states);
    cudaGetSymbolAddress((void**)&prefix, g_prefix);
    cudaGetSymbolAddress((void**)&y, g_y);

    gemm_tf32<<<dim3((DPROJ + BN - 1) / BN, NTOK / BM), 256>>>(x_seq, in_proj_w, zx, NTOK, DPROJ, DMODEL);
    conv_kernel<<<(NTOK * CONVDIM) / 256, 256>>>(zx, conv_w, conv_b, xbc);
    dt_acum_kernel<<<dim3(B_SZ * NCH, NH), CHUNK>>>(zx, dt_bias, A_log, dtp, acum);
    ydiag_mma<<<dim3(B_SZ * NCH, NH, 4), 128, 49152>>>(xbc, dtp, acum, y);
    states_mma<<<dim3(B_SZ * NCH, NH), 128>>>(xbc, dtp, acum, states);
    scan_kernel<<<dim3(B_SZ, NH), 256>>>(acum, states, prefix);
    yoff_mma<<<dim3(B_SZ * NCH, NH, 4), 128>>>(xbc, prefix, acum, Dv, y);
    gate_norm_kernel<<<NTOK, 256>>>(zx, norm_w, y);
    gemm_tf32<<<dim3(DMODEL / BN, NTOK / BM), 256>>>(y, out_proj_w, out, NTOK, DMODEL, DIN);
}

// round 10
// speedup vs baseline: 2.1114x; 1.3244x over previous
#include <cuda_runtime.h>
#include <math.h>
#include <stdint.h>

#define B_SZ   4
#define SEQ    4096
#define DMODEL 512
#define DIN    1024
#define NH     16
#define HD     64
#define DS     64
#define NCH    16
#define CHUNK  256
#define CONVDIM 1152
#define DPROJ  2192
#define NTOK   (B_SZ*SEQ)   // 16384

// ---------------- scratch (device globals; no runtime alloc) ----------------
__device__ float g_zx[(size_t)NTOK*DPROJ];
__device__ float g_xbc[(size_t)NTOK*CONVDIM];
__device__ float g_dt[NTOK*NH];
__device__ float g_acum[B_SZ*NCH*NH*CHUNK];
__device__ float g_states[B_SZ*NCH*NH*HD*DS];
__device__ float g_prefix[B_SZ*NCH*NH*HD*DS];
__device__ float g_y[(size_t)NTOK*DIN];

// ---------------- tf32 helpers (used by SSD kernels) ----------------
__device__ __forceinline__ uint32_t cvt_tf32(float f) {
    uint32_t r; asm("cvt.rna.tf32.f32 %0, %1;" : "=r"(r) : "f"(f)); return r;
}
__device__ __forceinline__ float tf32r(float f) { return __uint_as_float(cvt_tf32(f)); }

__device__ __forceinline__ void mma8(float* c, const float* a, const float* b) {
    asm volatile("mma.sync.aligned.m16n8k8.row.col.f32.tf32.tf32.f32 "
        "{%0,%1,%2,%3}, {%4,%5,%6,%7}, {%8,%9}, {%0,%1,%2,%3};"
        : "+f"(c[0]), "+f"(c[1]), "+f"(c[2]), "+f"(c[3])
        : "r"(__float_as_uint(a[0])), "r"(__float_as_uint(a[1])),
          "r"(__float_as_uint(a[2])), "r"(__float_as_uint(a[3])),
          "r"(__float_as_uint(b[0])), "r"(__float_as_uint(b[1])));
}

// bf16 m16n8k16 MMA
__device__ __forceinline__ void mma_bf16(float* c, const uint32_t* a, const uint32_t* b) {
    asm volatile("mma.sync.aligned.m16n8k16.row.col.f32.bf16.bf16.f32 "
        "{%0,%1,%2,%3}, {%4,%5,%6,%7}, {%8,%9}, {%0,%1,%2,%3};"
        : "+f"(c[0]), "+f"(c[1]), "+f"(c[2]), "+f"(c[3])
        : "r"(a[0]), "r"(a[1]), "r"(a[2]), "r"(a[3]), "r"(b[0]), "r"(b[1]));
}

// split float2 (two consecutive k-elements) into packed bf16x2 hi/lo (truncation split)
__device__ __forceinline__ void bsplit2(float2 p, uint32_t& hi, uint32_t& lo) {
    uint32_t ux = __float_as_uint(p.x), uy = __float_as_uint(p.y);
    hi = __byte_perm(ux, uy, 0x7632);            // {uy.hi16, ux.hi16}
    float rx = p.x - __uint_as_float(ux & 0xffff0000u);
    float ry = p.y - __uint_as_float(uy & 0xffff0000u);
    lo = __byte_perm(__float_as_uint(rx), __float_as_uint(ry), 0x7632);
}

// swizzled index into a [64][64] tile: element (r, c)
__device__ __forceinline__ int sw64(int r, int c) {
    return r * 64 + ((((c >> 2) ^ (r & 7)) << 2) | (c & 3));
}

// ======================= bf16x3 MMA GEMM: C[M,N] = A[M,K] @ B[N,K]^T =======================
#define BM 128
#define BN 64
#define BK 32

__device__ __forceinline__ int swz(int r, int k) {
    return r * 32 + ((((k >> 2) ^ (r & 7)) << 2) | (k & 3));
}

__global__ __launch_bounds__(256) void gemm_bf16x3(const float* __restrict__ A,
                                                   const float* __restrict__ Bw,
                                                   float* __restrict__ C,
                                                   int M, int N, int K) {
    __shared__ float As[2][BM * 32];
    __shared__ float Bs[2][BN * 32];
    int tid = threadIdx.x, lane = tid & 31, wid = tid >> 5;
    int wm = wid >> 1, wn = wid & 1;
    int g = lane >> 2, tg = lane & 3;
    int rowBase = blockIdx.y * BM, colBase = blockIdx.x * BN;

    float acc[2][4][4];
#pragma unroll
    for (int i = 0; i < 2; i++)
#pragma unroll
        for (int j = 0; j < 4; j++)
#pragma unroll
            for (int q = 0; q < 4; q++) acc[i][j][q] = 0.f;

    int KT = K / BK;
    auto loadTile = [&](int buf, int k0) {
#pragma unroll
        for (int q = 0; q < 4; q++) {
            int idx = tid + q * 256;
            int r = idx >> 3, c4 = idx & 7;
            uint32_t dst = (uint32_t)__cvta_generic_to_shared(&As[buf][r * 32 + ((c4 ^ (r & 7)) << 2)]);
            const float* src = &A[(size_t)(rowBase + r) * K + k0 + c4 * 4];
            asm volatile("cp.async.ca.shared.global [%0], [%1], 16;" :: "r"(dst), "l"(src));
        }
#pragma unroll
        for (int q = 0; q < 2; q++) {
            int idx = tid + q * 256;
            int r = idx >> 3, c4 = idx & 7;
            int nrow = colBase + r;
            uint32_t dst = (uint32_t)__cvta_generic_to_shared(&Bs[buf][r * 32 + ((c4 ^ (r & 7)) << 2)]);
            const float* src = &Bw[(size_t)(nrow < N ? nrow : 0) * K + k0 + c4 * 4];
            int sz = (nrow < N) ? 16 : 0;
            asm volatile("cp.async.ca.shared.global [%0], [%1], 16, %2;" :: "r"(dst), "l"(src), "r"(sz));
        }
        asm volatile("cp.async.commit_group;");
    };

    loadTile(0, 0);
    for (int kt = 0; kt < KT; kt++) {
        if (kt + 1 < KT) {
            loadTile((kt + 1) & 1, (kt + 1) * BK);
            asm volatile("cp.async.wait_group 1;");
        } else {
            asm volatile("cp.async.wait_group 0;");
        }
        __syncthreads();
        const float* as = As[kt & 1];
        const float* bs = Bs[kt & 1];
#pragma unroll
        for (int k16 = 0; k16 < BK / 16; k16++) {
            int kb = k16 * 16;
            uint32_t ahi[2][4], alo[2][4];
#pragma unroll
            for (int tm = 0; tm < 2; tm++) {
                int m0 = wm * 32 + tm * 16;
                float2 p00 = *(const float2*)&as[swz(m0 + g,     kb + 2 * tg)];
                float2 p10 = *(const float2*)&as[swz(m0 + g + 8, kb + 2 * tg)];
                float2 p01 = *(const float2*)&as[swz(m0 + g,     kb + 2 * tg + 8)];
                float2 p11 = *(const float2*)&as[swz(m0 + g + 8, kb + 2 * tg + 8)];
                bsplit2(p00, ahi[tm][0], alo[tm][0]);
                bsplit2(p10, ahi[tm][1], alo[tm][1]);
                bsplit2(p01, ahi[tm][2], alo[tm][2]);
                bsplit2(p11, ahi[tm][3], alo[tm][3]);
            }
            uint32_t bhi[4][2], blo[4][2];
#pragma unroll
            for (int tn = 0; tn < 4; tn++) {
                int n0 = wn * 32 + tn * 8;
                float2 q0 = *(const float2*)&bs[swz(n0 + g, kb + 2 * tg)];
                float2 q1 = *(const float2*)&bs[swz(n0 + g, kb + 2 * tg + 8)];
                bsplit2(q0, bhi[tn][0], blo[tn][0]);
                bsplit2(q1, bhi[tn][1], blo[tn][1]);
            }
#pragma unroll
            for (int tm = 0; tm < 2; tm++)
#pragma unroll
                for (int tn = 0; tn < 4; tn++) {
                    mma_bf16(acc[tm][tn], ahi[tm], bhi[tn]);
                    mma_bf16(acc[tm][tn], ahi[tm], blo[tn]);
                    mma_bf16(acc[tm][tn], alo[tm], bhi[tn]);
                }
        }
        __syncthreads();
    }
#pragma unroll
    for (int tm = 0; tm < 2; tm++) {
        int r0 = rowBase + wm * 32 + tm * 16;
#pragma unroll
        for (int tn = 0; tn < 4; tn++) {
            int c0 = colBase + wn * 32 + tn * 8 + tg * 2;
            if (c0 < N) {
                *(float2*)&C[(size_t)(r0 + g) * N + c0]     = make_float2(acc[tm][tn][0], acc[tm][tn][1]);
                *(float2*)&C[(size_t)(r0 + g + 8) * N + c0] = make_float2(acc[tm][tn][2], acc[tm][tn][3]);
            }
        }
    }
}

// ---------------- causal conv1d (width 4) + SiLU, sliding-window 4 l-positions/thread ----------------
__global__ __launch_bounds__(256) void conv_kernel(const float* __restrict__ zx,
                                                   const float* __restrict__ conv_w,
                                                   const float* __restrict__ conv_b,
                                                   float* __restrict__ xbc) {
    int idx = blockIdx.x * 256 + threadIdx.x;     // over (NTOK/4)*CONVDIM
    int c = idx % CONVDIM;
    int bl4 = idx / CONVDIM;                      // 0 .. NTOK/4-1
    int b = bl4 / (SEQ / 4);
    int l0 = (bl4 % (SEQ / 4)) * 4;

    float w0 = conv_w[c * 4 + 0], w1 = conv_w[c * 4 + 1];
    float w2 = conv_w[c * 4 + 2], w3 = conv_w[c * 4 + 3];
    float bias = conv_b[c];

    float v[7];
#pragma unroll
    for (int k = 0; k < 7; k++) {
        int ls = l0 - 3 + k;
        v[k] = (ls >= 0) ? zx[(size_t)(b * SEQ + ls) * DPROJ + DIN + c] : 0.f;
    }
#pragma unroll
    for (int j = 0; j < 4; j++) {
        float a = bias + v[j] * w0 + v[j + 1] * w1 + v[j + 2] * w2 + v[j + 3] * w3;
        xbc[(size_t)(b * SEQ + l0 + j) * CONVDIM + c] = a / (1.f + __expf(-a));
    }
}

// ---------------- dt softplus + per-chunk cumsum of dt*A ----------------
__global__ __launch_bounds__(256) void dt_acum_kernel(const float* __restrict__ zx,
                                                      const float* __restrict__ dt_bias,
                                                      const float* __restrict__ A_log,
                                                      float* __restrict__ dtp,
                                                      float* __restrict__ acum) {
    int bc = blockIdx.x;
    int h = blockIdx.y;
    int b = bc >> 4, c = bc & 15;
    int l = threadIdx.x;
    int row = b * SEQ + c * CHUNK + l;
    float x = zx[(size_t)row * DPROJ + (DPROJ - NH) + h] + dt_bias[h];
    float dtv = (x > 20.f) ? x : log1pf(expf(x));
    dtp[row * NH + h] = dtv;
    float a = -expf(A_log[h]) * dtv;

    __shared__ float s[CHUNK];
    s[l] = a;
    __syncthreads();
#pragma unroll
    for (int off = 1; off < CHUNK; off <<= 1) {
        float v = (l >= off) ? s[l - off] : 0.f;
        __syncthreads();
        s[l] += v;
        __syncthreads();
    }
    acum[(bc * NH + h) * CHUNK + l] = s[l];
}

// =================== MMA intra-chunk Y_diag, 64x64 tiles ===================
// dynamic smem = EXACTLY 49152 bytes (3 x 16KB), ZERO static smem.
__global__ __launch_bounds__(128) void ydiag_mma(const float* __restrict__ xbc,
                                                 const float* __restrict__ dtp,
                                                 const float* __restrict__ acum,
                                                 float* __restrict__ y) {
    extern __shared__ float sm[];
    float* sB = sm;            // [64][64] swizzled, tf32 B rows
    float* sX = sm + 4096;     // [64][64] swizzled, tf32 (x*dt)
    float* sS = sm + 8192;     // [64][64] swizzled, tf32 masked S (warp-private rows)

    int bc = blockIdx.x, h = blockIdx.y, lt = blockIdx.z;
    int b = bc >> 4, c = bc & 15;
    int rowBase = b * SEQ + c * CHUNK;
    int tid = threadIdx.x, lane = tid & 31, w = tid >> 5;
    int g = lane >> 2, tg = lane & 3;
    int lbase = lt * 64;
    const float* acbase = &acum[(bc * NH + h) * CHUNK];

    float creg[8][4];
    {
        const float* c0 = &xbc[(size_t)(rowBase + lbase + w * 16 + g) * CONVDIM + DIN + DS];
        const float* c1 = &xbc[(size_t)(rowBase + lbase + w * 16 + g + 8) * CONVDIM + DIN + DS];
#pragma unroll
        for (int kb8 = 0; kb8 < 8; kb8++) {
            int kb = kb8 * 8;
            creg[kb8][0] = tf32r(c0[kb + tg]);
            creg[kb8][1] = tf32r(c1[kb + tg]);
            creg[kb8][2] = tf32r(c0[kb + tg + 4]);
            creg[kb8][3] = tf32r(c1[kb + tg + 4]);
        }
    }
    float aL0 = acbase[lbase + w * 16 + g];
    float aL1 = acbase[lbase + w * 16 + g + 8];
    int lg0 = lbase + w * 16 + g, lg1 = lg0 + 8;

    float accY[8][4];
#pragma unroll
    for (int nt = 0; nt < 8; nt++)
#pragma unroll
        for (int q = 0; q < 4; q++) accY[nt][q] = 0.f;

    for (int st = 0; st <= lt; st++) {
        __syncthreads();
        int sbase = st * 64;
        for (int i = tid; i < 64 * 16; i += 128) {
            int r = i >> 4, q = (i & 15) * 4;
            size_t grow = (size_t)(rowBase + sbase + r);
            float4 bv = *(const float4*)&xbc[grow * CONVDIM + DIN + q];
            float4 bt = make_float4(tf32r(bv.x), tf32r(bv.y), tf32r(bv.z), tf32r(bv.w));
            *(float4*)&sB[r * 64 + ((((q >> 2) ^ (r & 7)) << 2))] = bt;
            float dtv = dtp[grow * NH + h];
            float4 xv = *(const float4*)&xbc[grow * CONVDIM + h * HD + q];
            float4 xt = make_float4(tf32r(xv.x * dtv), tf32r(xv.y * dtv),
                                    tf32r(xv.z * dtv), tf32r(xv.w * dtv));
            *(float4*)&sX[r * 64 + ((((q >> 2) ^ (r & 7)) << 2))] = xt;
        }
        __syncthreads();

        // stage 1: S = C @ B^T   (64x64x64)
        float accS[8][4];
#pragma unroll
        for (int nt = 0; nt < 8; nt++)
#pragma unroll
            for (int q = 0; q < 4; q++) accS[nt][q] = 0.f;
#pragma unroll
        for (int kb8 = 0; kb8 < 8; kb8++) {
            int kb = kb8 * 8;
#pragma unroll
            for (int nt = 0; nt < 8; nt++) {
                float bf[2] = { sB[sw64(nt * 8 + g, kb + tg)],
                                sB[sw64(nt * 8 + g, kb + tg + 4)] };
                mma8(accS[nt], creg[kb8], bf);
            }
        }
        // mask + decay -> warp-private sS rows (tf32); acum values from gmem (L1-hot)
#pragma unroll
        for (int nt = 0; nt < 8; nt++) {
            int col0 = nt * 8 + 2 * tg;
            int s0 = sbase + col0, s1 = s0 + 1;
            float as0 = __ldg(&acbase[s0]), as1 = __ldg(&acbase[s1]);
            float w00 = (s0 <= lg0) ? __expf(aL0 - as0) : 0.f;
            float w01 = (s1 <= lg0) ? __expf(aL0 - as1) : 0.f;
            float w10 = (s0 <= lg1) ? __expf(aL1 - as0) : 0.f;
            float w11 = (s1 <= lg1) ? __expf(aL1 - as1) : 0.f;
            *(float2*)&sS[sw64(w * 16 + g, col0)] =
                make_float2(tf32r(accS[nt][0] * w00), tf32r(accS[nt][1] * w01));
            *(float2*)&sS[sw64(w * 16 + g + 8, col0)] =
                make_float2(tf32r(accS[nt][2] * w10), tf32r(accS[nt][3] * w11));
        }
        __syncwarp();

        // stage 2: Y += S @ X   (64x64x64)
#pragma unroll
        for (int kb8 = 0; kb8 < 8; kb8++) {
            int kb = kb8 * 8;
            float a[4];
            a[0] = sS[sw64(w * 16 + g, kb + tg)];
            a[1] = sS[sw64(w * 16 + g + 8, kb + tg)];
            a[2] = sS[sw64(w * 16 + g, kb + tg + 4)];
            a[3] = sS[sw64(w * 16 + g + 8, kb + tg + 4)];
#pragma unroll
            for (int nt = 0; nt < 8; nt++) {
                float bf[2] = { sX[sw64(kb + tg, nt * 8 + g)],
                                sX[sw64(kb + tg + 4, nt * 8 + g)] };
                mma8(accY[nt], a, bf);
            }
        }
    }
    size_t r0 = (size_t)(rowBase + lbase + w * 16 + g);
#pragma unroll
    for (int nt = 0; nt < 8; nt++) {
        int col = h * HD + nt * 8 + 2 * tg;
        *(float2*)&y[r0 * DIN + col]       = make_float2(accY[nt][0], accY[nt][1]);
        *(float2*)&y[(r0 + 8) * DIN + col] = make_float2(accY[nt][2], accY[nt][3]);
    }
}

// =================== MMA per-chunk states: 32KB static smem ===================
__global__ __launch_bounds__(128) void states_mma(const float* __restrict__ xbc,
                                                  const float* __restrict__ dtp,
                                                  const float* __restrict__ acum,
                                                  float* __restrict__ states) {
    __shared__ float sX[4096];   // [64][64] swizzled (dec * x * dt)
    __shared__ float sB[4096];   // [64][64] swizzled

    int bc = blockIdx.x, h = blockIdx.y;
    int b = bc >> 4, c = bc & 15;
    int rowBase = b * SEQ + c * CHUNK;
    int tid = threadIdx.x, lane = tid & 31, w = tid >> 5;
    int g = lane >> 2, tg = lane & 3;
    int m0 = w * 16;
    const float* acbase = &acum[(bc * NH + h) * CHUNK];
    float aEnd = acbase[CHUNK - 1];

    float acc[8][4];
#pragma unroll
    for (int nt = 0; nt < 8; nt++)
#pragma unroll
        for (int q = 0; q < 4; q++) acc[nt][q] = 0.f;

    for (int st = 0; st < 4; st++) {
        __syncthreads();
        int sbase = st * 64;
        for (int i = tid; i < 64 * 16; i += 128) {
            int r = i >> 4, q = (i & 15) * 4;
            size_t grow = (size_t)(rowBase + sbase + r);
            float dec = __expf(aEnd - acbase[sbase + r]);
            float dtv = dtp[grow * NH + h] * dec;
            float4 xv = *(const float4*)&xbc[grow * CONVDIM + h * HD + q];
            float4 xt = make_float4(tf32r(xv.x * dtv), tf32r(xv.y * dtv),
                                    tf32r(xv.z * dtv), tf32r(xv.w * dtv));
            *(float4*)&sX[r * 64 + ((((q >> 2) ^ (r & 7)) << 2))] = xt;
            float4 bv = *(const float4*)&xbc[grow * CONVDIM + DIN + q];
            float4 bt = make_float4(tf32r(bv.x), tf32r(bv.y), tf32r(bv.z), tf32r(bv.w));
            *(float4*)&sB[r * 64 + ((((q >> 2) ^ (r & 7)) << 2))] = bt;
        }
        __syncthreads();
#pragma unroll
        for (int kb8 = 0; kb8 < 8; kb8++) {
            int kb = kb8 * 8;
            float a[4];
            a[0] = sX[sw64(kb + tg, m0 + g)];
            a[1] = sX[sw64(kb + tg, m0 + g + 8)];
            a[2] = sX[sw64(kb + tg + 4, m0 + g)];
            a[3] = sX[sw64(kb + tg + 4, m0 + g + 8)];
#pragma unroll
            for (int nt = 0; nt < 8; nt++) {
                float bf[2] = { sB[sw64(nt * 8 + g, kb + tg)],
                                sB[sw64(nt * 8 + g, kb + tg + 4)] };
                mma8(acc[nt], a, bf);
            }
        }
    }
    size_t base = (size_t)(bc * NH + h) * (HD * DS);
#pragma unroll
    for (int nt = 0; nt < 8; nt++) {
        int col = nt * 8 + 2 * tg;
        *(float2*)&states[base + (m0 + g) * DS + col]     = make_float2(acc[nt][0], acc[nt][1]);
        *(float2*)&states[base + (m0 + g + 8) * DS + col] = make_float2(acc[nt][2], acc[nt][3]);
    }
}

// ---------------- inter-chunk sequential scan ----------------
__global__ __launch_bounds__(256) void scan_kernel(const float* __restrict__ acum,
                                                   const float* __restrict__ states,
                                                   float* __restrict__ prefix) {
    int b = blockIdx.x, h = blockIdx.y, t = threadIdx.x;
    float S[16];
#pragma unroll
    for (int j = 0; j < 16; j++) S[j] = 0.f;
    for (int c = 0; c < NCH; c++) {
        size_t base = ((size_t)((b * NCH + c) * NH + h)) * (HD * DS) + t * 16;
#pragma unroll
        for (int j = 0; j < 16; j += 4) {
            float4 v = make_float4(S[j], S[j + 1], S[j + 2], S[j + 3]);
            *(float4*)&prefix[base + j] = v;
        }
        float cs = __expf(acum[((b * NCH + c) * NH + h) * CHUNK + (CHUNK - 1)]);
#pragma unroll
        for (int j = 0; j < 16; j += 4) {
            float4 sv = *(const float4*)&states[base + j];
            S[j + 0] = cs * S[j + 0] + sv.x;
            S[j + 1] = cs * S[j + 1] + sv.y;
            S[j + 2] = cs * S[j + 2] + sv.z;
            S[j + 3] = cs * S[j + 3] + sv.w;
        }
    }
}

// =================== MMA Y_off + D*xh: 16KB static smem, C-frags in registers ===================
__global__ __launch_bounds__(128) void yoff_mma(const float* __restrict__ xbc,
                                                const float* __restrict__ prefix,
                                                const float* __restrict__ acum,
                                                const float* __restrict__ Dv,
                                                float* __restrict__ y) {
    __shared__ float sP[4096];   // [64][64] swizzled, rows = p, cols = n

    int bc = blockIdx.x, h = blockIdx.y, lt = blockIdx.z;
    int b = bc >> 4, c = bc & 15;
    int rowBase = b * SEQ + c * CHUNK;
    int tid = threadIdx.x, lane = tid & 31, w = tid >> 5;
    int g = lane >> 2, tg = lane & 3;
    int lbase = lt * 64;

    size_t pbase = (size_t)(bc * NH + h) * (HD * DS);
    for (int i = tid; i < 64 * 16; i += 128) {
        int r = i >> 4, q = (i & 15) * 4;
        float4 v = *(const float4*)&prefix[pbase + r * DS + q];
        float4 vt = make_float4(tf32r(v.x), tf32r(v.y), tf32r(v.z), tf32r(v.w));
        *(float4*)&sP[r * 64 + ((((q >> 2) ^ (r & 7)) << 2))] = vt;
    }

    float creg[8][4];
    {
        const float* c0 = &xbc[(size_t)(rowBase + lbase + w * 16 + g) * CONVDIM + DIN + DS];
        const float* c1 = &xbc[(size_t)(rowBase + lbase + w * 16 + g + 8) * CONVDIM + DIN + DS];
#pragma unroll
        for (int kb8 = 0; kb8 < 8; kb8++) {
            int kb = kb8 * 8;
            creg[kb8][0] = tf32r(c0[kb + tg]);
            creg[kb8][1] = tf32r(c1[kb + tg]);
            creg[kb8][2] = tf32r(c0[kb + tg + 4]);
            creg[kb8][3] = tf32r(c1[kb + tg + 4]);
        }
    }
    __syncthreads();

    float acc[8][4];
#pragma unroll
    for (int nt = 0; nt < 8; nt++)
#pragma unroll
        for (int q = 0; q < 4; q++) acc[nt][q] = 0.f;

#pragma unroll
    for (int kb8 = 0; kb8 < 8; kb8++) {
        int kb = kb8 * 8;
#pragma unroll
        for (int nt = 0; nt < 8; nt++) {
            float bf[2] = { sP[sw64(nt * 8 + g, kb + tg)],
                            sP[sw64(nt * 8 + g, kb + tg + 4)] };
            mma8(acc[nt], creg[kb8], bf);
        }
    }

    float Dh = Dv[h];
    float ae0 = __expf(acum[(bc * NH + h) * CHUNK + lbase + w * 16 + g]);
    float ae1 = __expf(acum[(bc * NH + h) * CHUNK + lbase + w * 16 + g + 8]);
    size_t grow = (size_t)(rowBase + lbase + w * 16 + g);
#pragma unroll
    for (int nt = 0; nt < 8; nt++) {
        int col = h * HD + nt * 8 + 2 * tg;
        float2 yv0 = *(float2*)&y[grow * DIN + col];
        float2 xh0 = *(const float2*)&xbc[grow * CONVDIM + col];
        float2 yv1 = *(float2*)&y[(grow + 8) * DIN + col];
        float2 xh1 = *(const float2*)&xbc[(grow + 8) * CONVDIM + col];
        yv0.x += ae0 * acc[nt][0] + Dh * xh0.x;
        yv0.y += ae0 * acc[nt][1] + Dh * xh0.y;
        yv1.x += ae1 * acc[nt][2] + Dh * xh1.x;
        yv1.y += ae1 * acc[nt][3] + Dh * xh1.y;
        *(float2*)&y[grow * DIN + col] = yv0;
        *(float2*)&y[(grow + 8) * DIN + col] = yv1;
    }
}

// ---------------- gate with silu(z) + RMSNorm ----------------
__global__ __launch_bounds__(256) void gate_norm_kernel(const float* __restrict__ zx,
                                                        const float* __restrict__ norm_w,
                                                        float* __restrict__ y) {
    int row = blockIdx.x;
    int t = threadIdx.x;
    float4 yv = ((const float4*)&y[(size_t)row * DIN])[t];
    float4 zv = ((const float4*)&zx[(size_t)row * DPROJ])[t];
    float g0 = yv.x * (zv.x / (1.f + __expf(-zv.x)));
    float g1 = yv.y * (zv.y / (1.f + __expf(-zv.y)));
    float g2 = yv.z * (zv.z / (1.f + __expf(-zv.z)));
    float g3 = yv.w * (zv.w / (1.f + __expf(-zv.w)));
    float ss = g0 * g0 + g1 * g1 + g2 * g2 + g3 * g3;
#pragma unroll
    for (int o = 16; o; o >>= 1) ss += __shfl_xor_sync(0xffffffffu, ss, o);
    __shared__ float red[8];
    if ((t & 31) == 0) red[t >> 5] = ss;
    __syncthreads();
    float tot = red[0] + red[1] + red[2] + red[3] + red[4] + red[5] + red[6] + red[7];
    float rms = rsqrtf(tot / (float)DIN + 1e-5f);
    float4 nw = ((const float4*)norm_w)[t];
    float4 o = make_float4(g0 * rms * nw.x, g1 * rms * nw.y, g2 * rms * nw.z, g3 * rms * nw.w);
    ((float4*)&y[(size_t)row * DIN])[t] = o;
}

// ---------------- launch ----------------
extern "C" void kernel_launch(void* const* d_in, const int* in_sizes, int n_in,
                              void* d_out, int out_size) {
    const float* x_seq      = (const float*)d_in[0];
    const float* in_proj_w  = (const float*)d_in[1];
    const float* conv_w     = (const float*)d_in[2];
    const float* conv_b     = (const float*)d_in[3];
    const float* dt_bias    = (const float*)d_in[4];
    const float* A_log      = (const float*)d_in[5];
    const float* Dv         = (const float*)d_in[6];
    const float* norm_w     = (const float*)d_in[7];
    const float* out_proj_w = (const float*)d_in[8];
    float* out = (float*)d_out;

    float *zx, *xbc, *dtp, *acum, *states, *prefix, *y;
    cudaGetSymbolAddress((void**)&zx, g_zx);
    cudaGetSymbolAddress((void**)&xbc, g_xbc);
    cudaGetSymbolAddress((void**)&dtp, g_dt);
    cudaGetSymbolAddress((void**)&acum, g_acum);
    cudaGetSymbolAddress((void**)&states, g_states);
    cudaGetSymbolAddress((void**)&prefix, g_prefix);
    cudaGetSymbolAddress((void**)&y, g_y);

    gemm_bf16x3<<<dim3((DPROJ + BN - 1) / BN, NTOK / BM), 256>>>(x_seq, in_proj_w, zx, NTOK, DPROJ, DMODEL);
    conv_kernel<<<(NTOK / 4 * CONVDIM) / 256, 256>>>(zx, conv_w, conv_b, xbc);
    dt_acum_kernel<<<dim3(B_SZ * NCH, NH), CHUNK>>>(zx, dt_bias, A_log, dtp, acum);
    ydiag_mma<<<dim3(B_SZ * NCH, NH, 4), 128, 49152>>>(xbc, dtp, acum, y);
    states_mma<<<dim3(B_SZ * NCH, NH), 128>>>(xbc, dtp, acum, states);
    scan_kernel<<<dim3(B_SZ, NH), 256>>>(acum, states, prefix);
    yoff_mma<<<dim3(B_SZ * NCH, NH, 4), 128>>>(xbc, prefix, acum, Dv, y);
    gate_norm_kernel<<<NTOK, 256>>>(zx, norm_w, y);
    gemm_bf16x3<<<dim3(DMODEL / BN, NTOK / BM), 256>>>(y, out_proj_w, out, NTOK, DMODEL, DIN);
}

// round 12
// speedup vs baseline: 2.6064x; 1.2344x over previous
#include <cuda_runtime.h>
#include <math.h>
#include <stdint.h>

#define B_SZ   4
#define SEQ    4096
#define DMODEL 512
#define DIN    1024
#define NH     16
#define HD     64
#define DS     64
#define NCH    16
#define CHUNK  256
#define CONVDIM 1152
#define DPROJ  2192
#define NTOK   (B_SZ*SEQ)   // 16384

// ---------------- scratch (device globals; no runtime alloc) ----------------
__device__ float g_zx[(size_t)NTOK*DPROJ];
__device__ float g_xbc[(size_t)NTOK*CONVDIM];
__device__ float g_dt[NTOK*NH];
__device__ float g_acum[B_SZ*NCH*NH*CHUNK];
__device__ float g_states[B_SZ*NCH*NH*HD*DS];
__device__ float g_prefix[B_SZ*NCH*NH*HD*DS];
__device__ float g_y[(size_t)NTOK*DIN];
// bf16 hi/lo split buffers (act: up to 16384x1024 elems; w: up to 2192x512)
__device__ uint2 g_act_hi[(size_t)NTOK*DIN/4];
__device__ uint2 g_act_lo[(size_t)NTOK*DIN/4];
__device__ uint2 g_w_hi[(DPROJ*DMODEL)/4];
__device__ uint2 g_w_lo[(DPROJ*DMODEL)/4];

// ---------------- tf32 helpers (SSD kernels) ----------------
__device__ __forceinline__ uint32_t cvt_tf32(float f) {
    uint32_t r; asm("cvt.rna.tf32.f32 %0, %1;" : "=r"(r) : "f"(f)); return r;
}
__device__ __forceinline__ float tf32r(float f) { return __uint_as_float(cvt_tf32(f)); }

__device__ __forceinline__ void mma8(float* c, const float* a, const float* b) {
    asm volatile("mma.sync.aligned.m16n8k8.row.col.f32.tf32.tf32.f32 "
        "{%0,%1,%2,%3}, {%4,%5,%6,%7}, {%8,%9}, {%0,%1,%2,%3};"
        : "+f"(c[0]), "+f"(c[1]), "+f"(c[2]), "+f"(c[3])
        : "r"(__float_as_uint(a[0])), "r"(__float_as_uint(a[1])),
          "r"(__float_as_uint(a[2])), "r"(__float_as_uint(a[3])),
          "r"(__float_as_uint(b[0])), "r"(__float_as_uint(b[1])));
}
__device__ __forceinline__ void mma_bf16(float* c, const uint32_t* a, const uint32_t* b) {
    asm volatile("mma.sync.aligned.m16n8k16.row.col.f32.bf16.bf16.f32 "
        "{%0,%1,%2,%3}, {%4,%5,%6,%7}, {%8,%9}, {%0,%1,%2,%3};"
        : "+f"(c[0]), "+f"(c[1]), "+f"(c[2]), "+f"(c[3])
        : "r"(a[0]), "r"(a[1]), "r"(a[2]), "r"(a[3]), "r"(b[0]), "r"(b[1]));
}

// split float2 into packed bf16x2 hi/lo (truncation split)
__device__ __forceinline__ void bsplit2(float2 p, uint32_t& hi, uint32_t& lo) {
    uint32_t ux = __float_as_uint(p.x), uy = __float_as_uint(p.y);
    hi = __byte_perm(ux, uy, 0x7632);
    float rx = p.x - __uint_as_float(ux & 0xffff0000u);
    float ry = p.y - __uint_as_float(uy & 0xffff0000u);
    lo = __byte_perm(__float_as_uint(rx), __float_as_uint(ry), 0x7632);
}

__device__ __forceinline__ int sw64(int r, int c) {
    return r * 64 + ((((c >> 2) ^ (r & 7)) << 2) | (c & 3));
}
__device__ __forceinline__ uint32_t smem_u32(const void* p) {
    uint32_t a;
    asm("{ .reg .u64 t; cvta.to.shared.u64 t, %1; cvt.u32.u64 %0, t; }" : "=r"(a) : "l"(p));
    return a;
}
#define LDSM4(r0,r1,r2,r3,addr) \
    asm volatile("ldmatrix.sync.aligned.m8n8.x4.shared.b16 {%0,%1,%2,%3}, [%4];" \
        : "=r"(r0), "=r"(r1), "=r"(r2), "=r"(r3) : "r"(addr))

// ---------------- fp32 -> bf16 hi/lo split ----------------
__global__ __launch_bounds__(256) void split_kernel(const float4* __restrict__ src,
                                                    uint2* __restrict__ hi,
                                                    uint2* __restrict__ lo, int n4) {
    int i = blockIdx.x * 256 + threadIdx.x;
    if (i >= n4) return;
    float4 v = src[i];
    uint32_t h0, l0, h1, l1;
    bsplit2(make_float2(v.x, v.y), h0, l0);
    bsplit2(make_float2(v.z, v.w), h1, l1);
    hi[i] = make_uint2(h0, h1);
    lo[i] = make_uint2(l0, l1);
}

// ======= bf16 GEMM with pre-split inputs: C[M,N] = A @ B^T (hi*hi + hi*lo + lo*hi) =======
// tiles: BM=128, BN=64, BK=32. smem: double-buffered bf16 tiles, exactly 48KB.
// stage layout (bytes): Ahi[128x64B]=8K, Alo=8K, Bhi[64x64B]=4K, Blo=4K -> 24K/stage.
// chunk swizzle: 16B chunk c of row r stored at r*64 + ((c ^ ((r>>1)&3))<<4).
__global__ __launch_bounds__(256) void gemm_bf16ld(const uint16_t* __restrict__ Ahi,
                                                   const uint16_t* __restrict__ Alo,
                                                   const uint16_t* __restrict__ Bhi,
                                                   const uint16_t* __restrict__ Blo,
                                                   float* __restrict__ C,
                                                   int M, int N, int K) {
    __shared__ char smem[49152];
    uint32_t sb0 = smem_u32(smem);
    int tid = threadIdx.x, lane = tid & 31, wid = tid >> 5;
    int wm = wid >> 1, wn = wid & 1;
    int g = lane >> 2, tg = lane & 3;
    int rowBase = blockIdx.y * 128, colBase = blockIdx.x * 64;

    int sel = lane >> 3;
    int rowoff = ((sel & 1) << 3) + (lane & 7);
    int chsel = sel >> 1;

    float acc[2][4][4];
#pragma unroll
    for (int i = 0; i < 2; i++)
#pragma unroll
        for (int j = 0; j < 4; j++)
#pragma unroll
            for (int q = 0; q < 4; q++) acc[i][j][q] = 0.f;

    int KT = K >> 5;
    auto loadTile = [&](int buf, int k0) {
        uint32_t base = sb0 + buf * 24576;
        // A: 512 chunks (128 rows x 4 chunks of 8 bf16)
#pragma unroll
        for (int q = 0; q < 2; q++) {
            int i = tid + q * 256;
            int r = i >> 2, c = i & 3;
            uint32_t off = (uint32_t)(r * 64 + ((c ^ ((r >> 1) & 3)) << 4));
            const uint16_t* sh = &Ahi[(size_t)(rowBase + r) * K + k0 + c * 8];
            const uint16_t* sl = &Alo[(size_t)(rowBase + r) * K + k0 + c * 8];
            asm volatile("cp.async.ca.shared.global [%0], [%1], 16;" :: "r"(base + off), "l"(sh));
            asm volatile("cp.async.ca.shared.global [%0], [%1], 16;" :: "r"(base + 8192 + off), "l"(sl));
        }
        // B: 256 chunks (64 rows x 4 chunks)
        {
            int i = tid;
            int r = i >> 2, c = i & 3;
            int nrow = colBase + r;
            uint32_t off = (uint32_t)(r * 64 + ((c ^ ((r >> 1) & 3)) << 4));
            const uint16_t* sh = &Bhi[(size_t)(nrow < N ? nrow : 0) * K + k0 + c * 8];
            const uint16_t* sl = &Blo[(size_t)(nrow < N ? nrow : 0) * K + k0 + c * 8];
            int sz = (nrow < N) ? 16 : 0;
            asm volatile("cp.async.ca.shared.global [%0], [%1], 16, %2;" :: "r"(base + 16384 + off), "l"(sh), "r"(sz));
            asm volatile("cp.async.ca.shared.global [%0], [%1], 16, %2;" :: "r"(base + 20480 + off), "l"(sl), "r"(sz));
        }
        asm volatile("cp.async.commit_group;");
    };

    loadTile(0, 0);
    for (int kt = 0; kt < KT; kt++) {
        if (kt + 1 < KT) {
            loadTile((kt + 1) & 1, (kt + 1) * 32);
            asm volatile("cp.async.wait_group 1;");
        } else {
            asm volatile("cp.async.wait_group 0;");
        }
        __syncthreads();
        uint32_t base = sb0 + (kt & 1) * 24576;
#pragma unroll
        for (int kb16 = 0; kb16 < 2; kb16++) {
            int cbase = kb16 * 2;
            int ch = cbase + chsel;
            // A fragments (hi & lo) for 2 m-tiles
            uint32_t ah[2][4], al[2][4];
#pragma unroll
            for (int tm = 0; tm < 2; tm++) {
                int r = wm * 32 + tm * 16 + rowoff;
                uint32_t off = (uint32_t)(r * 64 + ((ch ^ ((r >> 1) & 3)) << 4));
                LDSM4(ah[tm][0], ah[tm][1], ah[tm][2], ah[tm][3], base + off);
                LDSM4(al[tm][0], al[tm][1], al[tm][2], al[tm][3], base + 8192 + off);
            }
            // B fragments: pairs of n8 tiles via x4
            uint32_t bh[4][2], bl[4][2];
#pragma unroll
            for (int pr = 0; pr < 2; pr++) {
                int r = wn * 32 + pr * 16 + rowoff;
                uint32_t off = (uint32_t)(r * 64 + ((ch ^ ((r >> 1) & 3)) << 4));
                uint32_t t0, t1, t2, t3;
                LDSM4(t0, t1, t2, t3, base + 16384 + off);
                bh[pr * 2][0] = t0; bh[pr * 2 + 1][0] = t1;
                bh[pr * 2][1] = t2; bh[pr * 2 + 1][1] = t3;
                LDSM4(t0, t1, t2, t3, base + 20480 + off);
                bl[pr * 2][0] = t0; bl[pr * 2 + 1][0] = t1;
                bl[pr * 2][1] = t2; bl[pr * 2 + 1][1] = t3;
            }
#pragma unroll
            for (int tm = 0; tm < 2; tm++)
#pragma unroll
                for (int tn = 0; tn < 4; tn++) {
                    mma_bf16(acc[tm][tn], ah[tm], bh[tn]);
                    mma_bf16(acc[tm][tn], ah[tm], bl[tn]);
                    mma_bf16(acc[tm][tn], al[tm], bh[tn]);
                }
        }
        __syncthreads();
    }
#pragma unroll
    for (int tm = 0; tm < 2; tm++) {
        int r0 = rowBase + wm * 32 + tm * 16;
#pragma unroll
        for (int tn = 0; tn < 4; tn++) {
            int c0 = colBase + wn * 32 + tn * 8 + tg * 2;
            if (c0 < N) {
                *(float2*)&C[(size_t)(r0 + g) * N + c0]     = make_float2(acc[tm][tn][0], acc[tm][tn][1]);
                *(float2*)&C[(size_t)(r0 + g + 8) * N + c0] = make_float2(acc[tm][tn][2], acc[tm][tn][3]);
            }
        }
    }
}

// ---------------- causal conv1d (width 4) + SiLU, sliding-window ----------------
__global__ __launch_bounds__(256) void conv_kernel(const float* __restrict__ zx,
                                                   const float* __restrict__ conv_w,
                                                   const float* __restrict__ conv_b,
                                                   float* __restrict__ xbc) {
    int idx = blockIdx.x * 256 + threadIdx.x;
    int c = idx % CONVDIM;
    int bl4 = idx / CONVDIM;
    int b = bl4 / (SEQ / 4);
    int l0 = (bl4 % (SEQ / 4)) * 4;

    float w0 = conv_w[c * 4 + 0], w1 = conv_w[c * 4 + 1];
    float w2 = conv_w[c * 4 + 2], w3 = conv_w[c * 4 + 3];
    float bias = conv_b[c];

    float v[7];
#pragma unroll
    for (int k = 0; k < 7; k++) {
        int ls = l0 - 3 + k;
        v[k] = (ls >= 0) ? zx[(size_t)(b * SEQ + ls) * DPROJ + DIN + c] : 0.f;
    }
#pragma unroll
    for (int j = 0; j < 4; j++) {
        float a = bias + v[j] * w0 + v[j + 1] * w1 + v[j + 2] * w2 + v[j + 3] * w3;
        xbc[(size_t)(b * SEQ + l0 + j) * CONVDIM + c] = a / (1.f + __expf(-a));
    }
}

// ---------------- dt softplus + per-chunk cumsum of dt*A ----------------
__global__ __launch_bounds__(256) void dt_acum_kernel(const float* __restrict__ zx,
                                                      const float* __restrict__ dt_bias,
                                                      const float* __restrict__ A_log,
                                                      float* __restrict__ dtp,
                                                      float* __restrict__ acum) {
    int bc = blockIdx.x;
    int h = blockIdx.y;
    int b = bc >> 4, c = bc & 15;
    int l = threadIdx.x;
    int row = b * SEQ + c * CHUNK + l;
    float x = zx[(size_t)row * DPROJ + (DPROJ - NH) + h] + dt_bias[h];
    float dtv = (x > 20.f) ? x : log1pf(expf(x));
    dtp[row * NH + h] = dtv;
    float a = -expf(A_log[h]) * dtv;

    __shared__ float s[CHUNK];
    s[l] = a;
    __syncthreads();
#pragma unroll
    for (int off = 1; off < CHUNK; off <<= 1) {
        float v = (l >= off) ? s[l - off] : 0.f;
        __syncthreads();
        s[l] += v;
        __syncthreads();
    }
    acum[(bc * NH + h) * CHUNK + l] = s[l];
}

// =================== MMA intra-chunk Y_diag, 64x64 tiles ===================
__global__ __launch_bounds__(128) void ydiag_mma(const float* __restrict__ xbc,
                                                 const float* __restrict__ dtp,
                                                 const float* __restrict__ acum,
                                                 float* __restrict__ y) {
    extern __shared__ float sm[];
    float* sB = sm;
    float* sX = sm + 4096;
    float* sS = sm + 8192;

    int bc = blockIdx.x, h = blockIdx.y, lt = blockIdx.z;
    int b = bc >> 4, c = bc & 15;
    int rowBase = b * SEQ + c * CHUNK;
    int tid = threadIdx.x, lane = tid & 31, w = tid >> 5;
    int g = lane >> 2, tg = lane & 3;
    int lbase = lt * 64;
    const float* acbase = &acum[(bc * NH + h) * CHUNK];

    float creg[8][4];
    {
        const float* c0 = &xbc[(size_t)(rowBase + lbase + w * 16 + g) * CONVDIM + DIN + DS];
        const float* c1 = &xbc[(size_t)(rowBase + lbase + w * 16 + g + 8) * CONVDIM + DIN + DS];
#pragma unroll
        for (int kb8 = 0; kb8 < 8; kb8++) {
            int kb = kb8 * 8;
            creg[kb8][0] = tf32r(c0[kb + tg]);
            creg[kb8][1] = tf32r(c1[kb + tg]);
            creg[kb8][2] = tf32r(c0[kb + tg + 4]);
            creg[kb8][3] = tf32r(c1[kb + tg + 4]);
        }
    }
    float aL0 = acbase[lbase + w * 16 + g];
    float aL1 = acbase[lbase + w * 16 + g + 8];
    int lg0 = lbase + w * 16 + g, lg1 = lg0 + 8;

    float accY[8][4];
#pragma unroll
    for (int nt = 0; nt < 8; nt++)
#pragma unroll
        for (int q = 0; q < 4; q++) accY[nt][q] = 0.f;

    for (int st = 0; st <= lt; st++) {
        __syncthreads();
        int sbase = st * 64;
        for (int i = tid; i < 64 * 16; i += 128) {
            int r = i >> 4, q = (i & 15) * 4;
            size_t grow = (size_t)(rowBase + sbase + r);
            float4 bv = *(const float4*)&xbc[grow * CONVDIM + DIN + q];
            float4 bt = make_float4(tf32r(bv.x), tf32r(bv.y), tf32r(bv.z), tf32r(bv.w));
            *(float4*)&sB[r * 64 + ((((q >> 2) ^ (r & 7)) << 2))] = bt;
            float dtv = dtp[grow * NH + h];
            float4 xv = *(const float4*)&xbc[grow * CONVDIM + h * HD + q];
            float4 xt = make_float4(tf32r(xv.x * dtv), tf32r(xv.y * dtv),
                                    tf32r(xv.z * dtv), tf32r(xv.w * dtv));
            *(float4*)&sX[r * 64 + ((((q >> 2) ^ (r & 7)) << 2))] = xt;
        }
        __syncthreads();

        float accS[8][4];
#pragma unroll
        for (int nt = 0; nt < 8; nt++)
#pragma unroll
            for (int q = 0; q < 4; q++) accS[nt][q] = 0.f;
#pragma unroll
        for (int kb8 = 0; kb8 < 8; kb8++) {
            int kb = kb8 * 8;
#pragma unroll
            for (int nt = 0; nt < 8; nt++) {
                float bf[2] = { sB[sw64(nt * 8 + g, kb + tg)],
                                sB[sw64(nt * 8 + g, kb + tg + 4)] };
                mma8(accS[nt], creg[kb8], bf);
            }
        }
#pragma unroll
        for (int nt = 0; nt < 8; nt++) {
            int col0 = nt * 8 + 2 * tg;
            int s0 = sbase + col0, s1 = s0 + 1;
            float as0 = __ldg(&acbase[s0]), as1 = __ldg(&acbase[s1]);
            float w00 = (s0 <= lg0) ? __expf(aL0 - as0) : 0.f;
            float w01 = (s1 <= lg0) ? __expf(aL0 - as1) : 0.f;
            float w10 = (s0 <= lg1) ? __expf(aL1 - as0) : 0.f;
            float w11 = (s1 <= lg1) ? __expf(aL1 - as1) : 0.f;
            *(float2*)&sS[sw64(w * 16 + g, col0)] =
                make_float2(tf32r(accS[nt][0] * w00), tf32r(accS[nt][1] * w01));
            *(float2*)&sS[sw64(w * 16 + g + 8, col0)] =
                make_float2(tf32r(accS[nt][2] * w10), tf32r(accS[nt][3] * w11));
        }
        __syncwarp();

#pragma unroll
        for (int kb8 = 0; kb8 < 8; kb8++) {
            int kb = kb8 * 8;
            float a[4];
            a[0] = sS[sw64(w * 16 + g, kb + tg)];
            a[1] = sS[sw64(w * 16 + g + 8, kb + tg)];
            a[2] = sS[sw64(w * 16 + g, kb + tg + 4)];
            a[3] = sS[sw64(w * 16 + g + 8, kb + tg + 4)];
#pragma unroll
            for (int nt = 0; nt < 8; nt++) {
                float bf[2] = { sX[sw64(kb + tg, nt * 8 + g)],
                                sX[sw64(kb + tg + 4, nt * 8 + g)] };
                mma8(accY[nt], a, bf);
            }
        }
    }
    size_t r0 = (size_t)(rowBase + lbase + w * 16 + g);
#pragma unroll
    for (int nt = 0; nt < 8; nt++) {
        int col = h * HD + nt * 8 + 2 * tg;
        *(float2*)&y[r0 * DIN + col]       = make_float2(accY[nt][0], accY[nt][1]);
        *(float2*)&y[(r0 + 8) * DIN + col] = make_float2(accY[nt][2], accY[nt][3]);
    }
}

// =================== MMA per-chunk states ===================
__global__ __launch_bounds__(128) void states_mma(const float* __restrict__ xbc,
                                                  const float* __restrict__ dtp,
                                                  const float* __restrict__ acum,
                                                  float* __restrict__ states) {
    __shared__ float sX[4096];
    __shared__ float sB[4096];

    int bc = blockIdx.x, h = blockIdx.y;
    int b = bc >> 4, c = bc & 15;
    int rowBase = b * SEQ + c * CHUNK;
    int tid = threadIdx.x, lane = tid & 31, w = tid >> 5;
    int g = lane >> 2, tg = lane & 3;
    int m0 = w * 16;
    const float* acbase = &acum[(bc * NH + h) * CHUNK];
    float aEnd = acbase[CHUNK - 1];

    float acc[8][4];
#pragma unroll
    for (int nt = 0; nt < 8; nt++)
#pragma unroll
        for (int q = 0; q < 4; q++) acc[nt][q] = 0.f;

    for (int st = 0; st < 4; st++) {
        __syncthreads();
        int sbase = st * 64;
        for (int i = tid; i < 64 * 16; i += 128) {
            int r = i >> 4, q = (i & 15) * 4;
            size_t grow = (size_t)(rowBase + sbase + r);
            float dec = __expf(aEnd - acbase[sbase + r]);
            float dtv = dtp[grow * NH + h] * dec;
            float4 xv = *(const float4*)&xbc[grow * CONVDIM + h * HD + q];
            float4 xt = make_float4(tf32r(xv.x * dtv), tf32r(xv.y * dtv),
                                    tf32r(xv.z * dtv), tf32r(xv.w * dtv));
            *(float4*)&sX[r * 64 + ((((q >> 2) ^ (r & 7)) << 2))] = xt;
            float4 bv = *(const float4*)&xbc[grow * CONVDIM + DIN + q];
            float4 bt = make_float4(tf32r(bv.x), tf32r(bv.y), tf32r(bv.z), tf32r(bv.w));
            *(float4*)&sB[r * 64 + ((((q >> 2) ^ (r & 7)) << 2))] = bt;
        }
        __syncthreads();
#pragma unroll
        for (int kb8 = 0; kb8 < 8; kb8++) {
            int kb = kb8 * 8;
            float a[4];
            a[0] = sX[sw64(kb + tg, m0 + g)];
            a[1] = sX[sw64(kb + tg, m0 + g + 8)];
            a[2] = sX[sw64(kb + tg + 4, m0 + g)];
            a[3] = sX[sw64(kb + tg + 4, m0 + g + 8)];
#pragma unroll
            for (int nt = 0; nt < 8; nt++) {
                float bf[2] = { sB[sw64(nt * 8 + g, kb + tg)],
                                sB[sw64(nt * 8 + g, kb + tg + 4)] };
                mma8(acc[nt], a, bf);
            }
        }
    }
    size_t base = (size_t)(bc * NH + h) * (HD * DS);
#pragma unroll
    for (int nt = 0; nt < 8; nt++) {
        int col = nt * 8 + 2 * tg;
        *(float2*)&states[base + (m0 + g) * DS + col]     = make_float2(acc[nt][0], acc[nt][1]);
        *(float2*)&states[base + (m0 + g + 8) * DS + col] = make_float2(acc[nt][2], acc[nt][3]);
    }
}

// ---------------- inter-chunk sequential scan ----------------
__global__ __launch_bounds__(256) void scan_kernel(const float* __restrict__ acum,
                                                   const float* __restrict__ states,
                                                   float* __restrict__ prefix) {
    int b = blockIdx.x, h = blockIdx.y, t = threadIdx.x;
    float S[16];
#pragma unroll
    for (int j = 0; j < 16; j++) S[j] = 0.f;
    for (int c = 0; c < NCH; c++) {
        size_t base = ((size_t)((b * NCH + c) * NH + h)) * (HD * DS) + t * 16;
#pragma unroll
        for (int j = 0; j < 16; j += 4) {
            float4 v = make_float4(S[j], S[j + 1], S[j + 2], S[j + 3]);
            *(float4*)&prefix[base + j] = v;
        }
        float cs = __expf(acum[((b * NCH + c) * NH + h) * CHUNK + (CHUNK - 1)]);
#pragma unroll
        for (int j = 0; j < 16; j += 4) {
            float4 sv = *(const float4*)&states[base + j];
            S[j + 0] = cs * S[j + 0] + sv.x;
            S[j + 1] = cs * S[j + 1] + sv.y;
            S[j + 2] = cs * S[j + 2] + sv.z;
            S[j + 3] = cs * S[j + 3] + sv.w;
        }
    }
}

// =================== MMA Y_off + D*xh ===================
__global__ __launch_bounds__(128) void yoff_mma(const float* __restrict__ xbc,
                                                const float* __restrict__ prefix,
                                                const float* __restrict__ acum,
                                                const float* __restrict__ Dv,
                                                float* __restrict__ y) {
    __shared__ float sP[4096];

    int bc = blockIdx.x, h = blockIdx.y, lt = blockIdx.z;
    int b = bc >> 4, c = bc & 15;
    int rowBase = b * SEQ + c * CHUNK;
    int tid = threadIdx.x, lane = tid & 31, w = tid >> 5;
    int g = lane >> 2, tg = lane & 3;
    int lbase = lt * 64;

    size_t pbase = (size_t)(bc * NH + h) * (HD * DS);
    for (int i = tid; i < 64 * 16; i += 128) {
        int r = i >> 4, q = (i & 15) * 4;
        float4 v = *(const float4*)&prefix[pbase + r * DS + q];
        float4 vt = make_float4(tf32r(v.x), tf32r(v.y), tf32r(v.z), tf32r(v.w));
        *(float4*)&sP[r * 64 + ((((q >> 2) ^ (r & 7)) << 2))] = vt;
    }

    float creg[8][4];
    {
        const float* c0 = &xbc[(size_t)(rowBase + lbase + w * 16 + g) * CONVDIM + DIN + DS];
        const float* c1 = &xbc[(size_t)(rowBase + lbase + w * 16 + g + 8) * CONVDIM + DIN + DS];
#pragma unroll
        for (int kb8 = 0; kb8 < 8; kb8++) {
            int kb = kb8 * 8;
            creg[kb8][0] = tf32r(c0[kb + tg]);
            creg[kb8][1] = tf32r(c1[kb + tg]);
            creg[kb8][2] = tf32r(c0[kb + tg + 4]);
            creg[kb8][3] = tf32r(c1[kb + tg + 4]);
        }
    }
    __syncthreads();

    float acc[8][4];
#pragma unroll
    for (int nt = 0; nt < 8; nt++)
#pragma unroll
        for (int q = 0; q < 4; q++) acc[nt][q] = 0.f;

#pragma unroll
    for (int kb8 = 0; kb8 < 8; kb8++) {
        int kb = kb8 * 8;
#pragma unroll
        for (int nt = 0; nt < 8; nt++) {
            float bf[2] = { sP[sw64(nt * 8 + g, kb + tg)],
                            sP[sw64(nt * 8 + g, kb + tg + 4)] };
            mma8(acc[nt], creg[kb8], bf);
        }
    }

    float Dh = Dv[h];
    float ae0 = __expf(acum[(bc * NH + h) * CHUNK + lbase + w * 16 + g]);
    float ae1 = __expf(acum[(bc * NH + h) * CHUNK + lbase + w * 16 + g + 8]);
    size_t grow = (size_t)(rowBase + lbase + w * 16 + g);
#pragma unroll
    for (int nt = 0; nt < 8; nt++) {
        int col = h * HD + nt * 8 + 2 * tg;
        float2 yv0 = *(float2*)&y[grow * DIN + col];
        float2 xh0 = *(const float2*)&xbc[grow * CONVDIM + col];
        float2 yv1 = *(float2*)&y[(grow + 8) * DIN + col];
        float2 xh1 = *(const float2*)&xbc[(grow + 8) * CONVDIM + col];
        yv0.x += ae0 * acc[nt][0] + Dh * xh0.x;
        yv0.y += ae0 * acc[nt][1] + Dh * xh0.y;
        yv1.x += ae1 * acc[nt][2] + Dh * xh1.x;
        yv1.y += ae1 * acc[nt][3] + Dh * xh1.y;
        *(float2*)&y[grow * DIN + col] = yv0;
        *(float2*)&y[(grow + 8) * DIN + col] = yv1;
    }
}

// ---------------- gate with silu(z) + RMSNorm ----------------
__global__ __launch_bounds__(256) void gate_norm_kernel(const float* __restrict__ zx,
                                                        const float* __restrict__ norm_w,
                                                        float* __restrict__ y) {
    int row = blockIdx.x;
    int t = threadIdx.x;
    float4 yv = ((const float4*)&y[(size_t)row * DIN])[t];
    float4 zv = ((const float4*)&zx[(size_t)row * DPROJ])[t];
    float g0 = yv.x * (zv.x / (1.f + __expf(-zv.x)));
    float g1 = yv.y * (zv.y / (1.f + __expf(-zv.y)));
    float g2 = yv.z * (zv.z / (1.f + __expf(-zv.z)));
    float g3 = yv.w * (zv.w / (1.f + __expf(-zv.w)));
    float ss = g0 * g0 + g1 * g1 + g2 * g2 + g3 * g3;
#pragma unroll
    for (int o = 16; o; o >>= 1) ss += __shfl_xor_sync(0xffffffffu, ss, o);
    __shared__ float red[8];
    if ((t & 31) == 0) red[t >> 5] = ss;
    __syncthreads();
    float tot = red[0] + red[1] + red[2] + red[3] + red[4] + red[5] + red[6] + red[7];
    float rms = rsqrtf(tot / (float)DIN + 1e-5f);
    float4 nw = ((const float4*)norm_w)[t];
    float4 o = make_float4(g0 * rms * nw.x, g1 * rms * nw.y, g2 * rms * nw.z, g3 * rms * nw.w);
    ((float4*)&y[(size_t)row * DIN])[t] = o;
}

// ---------------- launch ----------------
extern "C" void kernel_launch(void* const* d_in, const int* in_sizes, int n_in,
                              void* d_out, int out_size) {
    const float* x_seq      = (const float*)d_in[0];
    const float* in_proj_w  = (const float*)d_in[1];
    const float* conv_w     = (const float*)d_in[2];
    const float* conv_b     = (const float*)d_in[3];
    const float* dt_bias    = (const float*)d_in[4];
    const float* A_log      = (const float*)d_in[5];
    const float* Dv         = (const float*)d_in[6];
    const float* norm_w     = (const float*)d_in[7];
    const float* out_proj_w = (const float*)d_in[8];
    float* out = (float*)d_out;

    float *zx, *xbc, *dtp, *acum, *states, *prefix, *y;
    uint2 *ah, *al, *wh, *wl;
    cudaGetSymbolAddress((void**)&zx, g_zx);
    cudaGetSymbolAddress((void**)&xbc, g_xbc);
    cudaGetSymbolAddress((void**)&dtp, g_dt);
    cudaGetSymbolAddress((void**)&acum, g_acum);
    cudaGetSymbolAddress((void**)&states, g_states);
    cudaGetSymbolAddress((void**)&prefix, g_prefix);
    cudaGetSymbolAddress((void**)&y, g_y);
    cudaGetSymbolAddress((void**)&ah, g_act_hi);
    cudaGetSymbolAddress((void**)&al, g_act_lo);
    cudaGetSymbolAddress((void**)&wh, g_w_hi);
    cudaGetSymbolAddress((void**)&wl, g_w_lo);

    // ---- in_proj: split inputs, then bf16 ldmatrix GEMM ----
    int n4x = NTOK * DMODEL / 4;        // 2,097,152
    int n4w1 = DPROJ * DMODEL / 4;      // 280,576
    split_kernel<<<n4x / 256, 256>>>((const float4*)x_seq, ah, al, n4x);
    split_kernel<<<(n4w1 + 255) / 256, 256>>>((const float4*)in_proj_w, wh, wl, n4w1);
    gemm_bf16ld<<<dim3((DPROJ + 63) / 64, NTOK / 128), 256>>>(
        (const uint16_t*)ah, (const uint16_t*)al, (const uint16_t*)wh, (const uint16_t*)wl,
        zx, NTOK, DPROJ, DMODEL);

    conv_kernel<<<(NTOK / 4 * CONVDIM) / 256, 256>>>(zx, conv_w, conv_b, xbc);
    dt_acum_kernel<<<dim3(B_SZ * NCH, NH), CHUNK>>>(zx, dt_bias, A_log, dtp, acum);
    ydiag_mma<<<dim3(B_SZ * NCH, NH, 4), 128, 49152>>>(xbc, dtp, acum, y);
    states_mma<<<dim3(B_SZ * NCH, NH), 128>>>(xbc, dtp, acum, states);
    scan_kernel<<<dim3(B_SZ, NH), 256>>>(acum, states, prefix);
    yoff_mma<<<dim3(B_SZ * NCH, NH, 4), 128>>>(xbc, prefix, acum, Dv, y);
    gate_norm_kernel<<<NTOK, 256>>>(zx, norm_w, y);

    // ---- out_proj: split y + weight, GEMM ----
    int n4y = NTOK * DIN / 4;           // 4,194,304
    int n4w2 = DMODEL * DIN / 4;        // 131,072
    split_kernel<<<n4y / 256, 256>>>((const float4*)y, ah, al, n4y);
    split_kernel<<<n4w2 / 256, 256>>>((const float4*)out_proj_w, wh, wl, n4w2);
    gemm_bf16ld<<<dim3(DMODEL / 64, NTOK / 128), 256>>>(
        (const uint16_t*)ah, (const uint16_t*)al, (const uint16_t*)wh, (const uint16_t*)wl,
        out, NTOK, DMODEL, DIN);
}